// round 2
// baseline (speedup 1.0000x reference)
#include <cuda_runtime.h>

#define SEQ   2048
#define NH    8
#define DH    640
#define DKV   128
#define NB    2
#define ROWS  (NB*SEQ)     // 4096
#define DM    5120
#define SPLITD 624

// ---------------- scratch (device globals; allocation-free) ----------------
__device__ float g_ckv[ROWS*DKV];
__device__ float g_cq [ROWS*DKV];
__device__ float g_kr [ROWS*DKV];
__device__ float g_qr [ROWS*DKV];
__device__ float g_q  [(size_t)NB*NH*SEQ*DH];     // [bh][s][640]
__device__ float g_k  [(size_t)NB*NH*SEQ*DH];
__device__ float g_v  [(size_t)NB*NH*SEQ*DH];
__device__ float g_sc [(size_t)NB*NH*SEQ*SEQ];    // [bh][s][s]  268MB
__device__ float g_ao [(size_t)ROWS*DM];          // [b][s][h*640]

// ---------------- generic SGEMM: C = A @ B (+bias), batched over z ----------
// TRANSB: B is [N,K] row-major (use B[n*ldb+k]); else [K,N] row-major.
// HEADMAP: write C[((b*NH+h)*SEQ+s)*DH + destOff + d] with h=c/headW,d=c%headW.
// Otherwise: C[cbase + r*ldc + c], cbase = (z/zdiv)*sC1 + (z%zdiv)*sC2.
template<bool TRANSB, bool HEADMAP>
__global__ void __launch_bounds__(256)
sgemm(const float* __restrict__ A, const float* __restrict__ B,
      const float* __restrict__ bias, float* __restrict__ C,
      int M, int N, int K, int lda, int ldb, int ldc,
      long long sA, long long sB, long long sC1, long long sC2, int zdiv,
      int headW, int destOff)
{
    int z = blockIdx.z;
    A += (long long)z * sA;
    B += (long long)z * sB;
    long long cbase = (long long)(z / zdiv) * sC1 + (long long)(z % zdiv) * sC2;

    __shared__ float As[8][128];
    __shared__ float Bs[8][128];

    int tid = threadIdx.x;
    int tr = tid >> 4;          // 0..15
    int tc = tid & 15;          // 0..15
    int row0 = blockIdx.y * 128;
    int col0 = blockIdx.x * 128;

    float acc[8][8];
    #pragma unroll
    for (int i = 0; i < 8; i++)
        #pragma unroll
        for (int j = 0; j < 8; j++) acc[i][j] = 0.0f;

    for (int k0 = 0; k0 < K; k0 += 8) {
        #pragma unroll
        for (int t = 0; t < 4; t++) {
            int idx = tid + t * 256;            // 0..1023
            int ar = idx >> 3, ak = idx & 7;
            As[ak][ar] = A[(long long)(row0 + ar) * lda + k0 + ak];
        }
        #pragma unroll
        for (int t = 0; t < 4; t++) {
            int idx = tid + t * 256;
            if (TRANSB) {
                int bn = idx >> 3, bk = idx & 7;
                Bs[bk][bn] = B[(long long)(col0 + bn) * ldb + k0 + bk];
            } else {
                int bk = idx >> 7, bn = idx & 127;
                Bs[bk][bn] = B[(long long)(k0 + bk) * ldb + col0 + bn];
            }
        }
        __syncthreads();
        #pragma unroll
        for (int k = 0; k < 8; k++) {
            float a[8], b[8];
            #pragma unroll
            for (int i = 0; i < 8; i++) a[i] = As[k][tr * 8 + i];
            #pragma unroll
            for (int j = 0; j < 8; j++) b[j] = Bs[k][tc * 8 + j];
            #pragma unroll
            for (int i = 0; i < 8; i++)
                #pragma unroll
                for (int j = 0; j < 8; j++)
                    acc[i][j] += a[i] * b[j];
        }
        __syncthreads();
    }

    #pragma unroll
    for (int i = 0; i < 8; i++) {
        int r = row0 + tr * 8 + i;
        #pragma unroll
        for (int j = 0; j < 8; j++) {
            int c = col0 + tc * 8 + j;
            float val = acc[i][j] + (bias ? bias[c] : 0.0f);
            if (HEADMAP) {
                int b_ = r / SEQ, s = r % SEQ;
                int h = c / headW, d = c % headW;
                C[(((long long)(b_ * NH + h)) * SEQ + s) * DH + destOff + d] = val;
            } else {
                C[cbase + (long long)r * ldc + c] = val;
            }
        }
    }
}

// ---------------- RoPE: rotate first 8 of 16 dims, scatter to dst[...,624:640]
__global__ void rope_scatter(const float* __restrict__ src, float* __restrict__ dst)
{
    int t = blockIdx.x * blockDim.x + threadIdx.x;
    if (t >= ROWS * NH) return;
    int r = t / NH, h = t % NH;
    int b_ = r / SEQ, s = r % SEQ;
    const float* x = src + (long long)r * (NH * 16) + h * 16;
    float* o = dst + (((long long)(b_ * NH + h)) * SEQ + s) * DH + SPLITD;

    float tpos = (float)s / 40.0f;
    #pragma unroll
    for (int j = 0; j < 4; j++) {
        float invf = powf(10000.0f, -0.25f * (float)j);
        float f = tpos * invf;
        float cs = cosf(f), sn = sinf(f);
        float x1 = x[j], x2 = x[j + 4];
        o[j]     = x1 * cs - x2 * sn;
        o[j + 4] = x2 * cs + x1 * sn;
    }
    #pragma unroll
    for (int j = 8; j < 16; j++) o[j] = x[j];
}

// ---------------- row softmax over 2048 cols (with 1/sqrt(640) scale) -------
__global__ void __launch_bounds__(256)
softmax_rows(float* __restrict__ sc)
{
    long long row = blockIdx.x;
    float* p = sc + row * SEQ;
    const float scale = rsqrtf(640.0f);
    int tid = threadIdx.x;
    __shared__ float red[256];

    float vals[8];
    float mx = -1e30f;
    #pragma unroll
    for (int i = 0; i < 8; i++) {
        vals[i] = p[tid + i * 256] * scale;
        mx = fmaxf(mx, vals[i]);
    }
    red[tid] = mx; __syncthreads();
    for (int s = 128; s > 0; s >>= 1) {
        if (tid < s) red[tid] = fmaxf(red[tid], red[tid + s]);
        __syncthreads();
    }
    mx = red[0]; __syncthreads();

    float sum = 0.0f;
    #pragma unroll
    for (int i = 0; i < 8; i++) { vals[i] = __expf(vals[i] - mx); sum += vals[i]; }
    red[tid] = sum; __syncthreads();
    for (int s = 128; s > 0; s >>= 1) {
        if (tid < s) red[tid] += red[tid + s];
        __syncthreads();
    }
    float inv = 1.0f / red[0];
    #pragma unroll
    for (int i = 0; i < 8; i++) p[tid + i * 256] = vals[i] * inv;
}

// ---------------- launch ----------------------------------------------------
extern "C" void kernel_launch(void* const* d_in, const int* in_sizes, int n_in,
                              void* d_out, int out_size)
{
    const float* h     = (const float*)d_in[0];
    const float* W_dkv = (const float*)d_in[1];
    const float* b_dkv = (const float*)d_in[2];
    const float* W_dq  = (const float*)d_in[3];
    const float* b_dq  = (const float*)d_in[4];
    const float* W_uk  = (const float*)d_in[5];
    const float* b_uk  = (const float*)d_in[6];
    const float* W_uv  = (const float*)d_in[7];
    const float* b_uv  = (const float*)d_in[8];
    const float* W_uq  = (const float*)d_in[9];
    const float* b_uq  = (const float*)d_in[10];
    const float* W_qr  = (const float*)d_in[11];
    const float* b_qr  = (const float*)d_in[12];
    const float* W_kr  = (const float*)d_in[13];
    const float* b_kr  = (const float*)d_in[14];
    const float* W_o   = (const float*)d_in[15];
    const float* b_o   = (const float*)d_in[16];
    float* out = (float*)d_out;

    float *ckv, *cq, *kr, *qr, *q, *k, *v, *sc, *ao;
    cudaGetSymbolAddress((void**)&ckv, g_ckv);
    cudaGetSymbolAddress((void**)&cq,  g_cq);
    cudaGetSymbolAddress((void**)&kr,  g_kr);
    cudaGetSymbolAddress((void**)&qr,  g_qr);
    cudaGetSymbolAddress((void**)&q,   g_q);
    cudaGetSymbolAddress((void**)&k,   g_k);
    cudaGetSymbolAddress((void**)&v,   g_v);
    cudaGetSymbolAddress((void**)&sc,  g_sc);
    cudaGetSymbolAddress((void**)&ao,  g_ao);

    const long long Z = 0;

    // 1) down-projections: [4096,5120] x [5120,128]
    sgemm<false,false><<<dim3(1,32,1),256>>>(h, W_dkv, b_dkv, ckv,
        ROWS,128,DM, DM,128,128, Z,Z,Z,Z,1, 0,0);
    sgemm<false,false><<<dim3(1,32,1),256>>>(h, W_dq, b_dq, cq,
        ROWS,128,DM, DM,128,128, Z,Z,Z,Z,1, 0,0);
    sgemm<false,false><<<dim3(1,32,1),256>>>(h, W_kr, b_kr, kr,
        ROWS,128,DM, DM,128,128, Z,Z,Z,Z,1, 0,0);

    // 2) up-projections (scatter into [B,H,S,640] layout)
    sgemm<false,true><<<dim3(39,32,1),256>>>(ckv, W_uk, b_uk, k,
        ROWS,NH*SPLITD,DKV, DKV,NH*SPLITD,0, Z,Z,Z,Z,1, SPLITD,0);
    sgemm<false,true><<<dim3(40,32,1),256>>>(ckv, W_uv, b_uv, v,
        ROWS,NH*DH,DKV, DKV,NH*DH,0, Z,Z,Z,Z,1, DH,0);
    sgemm<false,true><<<dim3(39,32,1),256>>>(cq, W_uq, b_uq, q,
        ROWS,NH*SPLITD,DKV, DKV,NH*SPLITD,0, Z,Z,Z,Z,1, SPLITD,0);
    sgemm<false,false><<<dim3(1,32,1),256>>>(cq, W_qr, b_qr, qr,
        ROWS,128,DKV, DKV,128,128, Z,Z,Z,Z,1, 0,0);

    // 3) RoPE scatter into q/k [...,624:640]
    rope_scatter<<<(ROWS*NH + 255)/256, 256>>>(qr, q);
    rope_scatter<<<(ROWS*NH + 255)/256, 256>>>(kr, k);

    // 4) scores = q @ k^T per head (z = bh), scale applied in softmax
    sgemm<true,false><<<dim3(16,16,16),256>>>(q, k, nullptr, sc,
        SEQ,SEQ,DH, DH,DH,SEQ,
        (long long)SEQ*DH, (long long)SEQ*DH, Z, (long long)SEQ*SEQ, 16, 0,0);

    // 5) softmax rows
    softmax_rows<<<NB*NH*SEQ, 256>>>(sc);

    // 6) attn @ v  -> ao[b][s][h*640]
    sgemm<false,false><<<dim3(5,16,16),256>>>(sc, v, nullptr, ao,
        SEQ,DH,SEQ, SEQ,DH,DM,
        (long long)SEQ*SEQ, (long long)SEQ*DH,
        (long long)SEQ*DM, (long long)DH, NH, 0,0);

    // 7) final: [4096,5120] x [5120,5120] + b_o
    sgemm<false,false><<<dim3(40,32,1),256>>>(ao, W_o, b_o, out,
        ROWS,DM,DM, DM,DM,DM, Z,Z,Z,Z,1, 0,0);
}

// round 4
// speedup vs baseline: 2.4301x; 2.4301x over previous
#include <cuda_runtime.h>
#include <cstdint>

#define SEQ   2048
#define NH    8
#define DH    640
#define DKV   128
#define NB    2
#define ROWS  (NB*SEQ)     // 4096
#define DM    5120
#define SPLITD 624
#define STAGES 3
#define STF   (128*36)         // floats per tile buffer (stride-36 pad)
#define STB   (STF*4)          // 18432 bytes
#define STAGE_B (2*STB)        // 36864 bytes (A+B)
#define SMEMB (STAGES*STAGE_B) // 110592 bytes

// ---------------- scratch (device globals; allocation-free) ----------------
__device__ float g_ckv[ROWS*DKV];
__device__ float g_cq [ROWS*DKV];
__device__ float g_kr [ROWS*DKV];
__device__ float g_qr [ROWS*DKV];
__device__ float g_q  [(size_t)NB*NH*SEQ*DH];     // [bh][s][640]
__device__ float g_k  [(size_t)NB*NH*SEQ*DH];     // [bh][s][640]
__device__ float g_v  [(size_t)NB*NH*SEQ*DH];     // [bh][s][640]
__device__ float g_vT [(size_t)NB*NH*DH*SEQ];     // [bh][d][s]
__device__ float g_sc [(size_t)NB*NH*SEQ*SEQ];    // [bh][s][s]
__device__ float g_ao [(size_t)ROWS*DM];          // [b][s][h*640]
// transposed weights (stored [N][K], K-major)
__device__ float g_WdkvT[DKV*DM];
__device__ float g_WdqT [DKV*DM];
__device__ float g_WkrT [(NH*16)*DM];
__device__ float g_WukT [(NH*SPLITD)*DKV];
__device__ float g_WuvT [(NH*DH)*DKV];
__device__ float g_WuqT [(NH*SPLITD)*DKV];
__device__ float g_WqrT [(NH*16)*DKV];
__device__ float g_WoT  [(size_t)DM*DM];

// ---------------- helpers ----------------------------------------------
__device__ __forceinline__ uint32_t smem_u32(const void* p) {
    uint32_t a;
    asm("{ .reg .u64 t; cvta.to.shared.u64 t, %1; cvt.u32.u64 %0, t; }"
        : "=r"(a) : "l"(p));
    return a;
}
__device__ __forceinline__ uint32_t f2tf32(float x) {
    uint32_t u;
    asm("cvt.rna.tf32.f32 %0, %1;" : "=r"(u) : "f"(x));
    return u;
}

// ---------------- tf32 mma.sync GEMM: C = A[M,K] @ B[N,K]^T (+bias) ---------
// CMODE 0: C[cbase + r*ldc + c], cbase = (z/zdiv)*sC1 + (z%zdiv)*sC2
// CMODE 1: headmap: C[((b*NH+h)*SEQ+s)*640 + destOff + d], h=c/headW, d=c%headW
template<int CMODE>
__global__ void __launch_bounds__(256, 1)
mma_gemm(const float* __restrict__ A, const float* __restrict__ B,
         const float* __restrict__ bias, float* __restrict__ C,
         int K, int lda, int ldb, int ldc,
         long long sA, long long sB, long long sC1, long long sC2, int zdiv,
         int headW, int destOff)
{
    extern __shared__ float sm[];
    const uint32_t sb = smem_u32(sm);
    const int tid = threadIdx.x, lane = tid & 31, wid = tid >> 5;
    const int wm = wid >> 2, wn = wid & 3;       // warp grid 2 (m) x 4 (n)
    const int z = blockIdx.z;
    A += (long long)z * sA;
    B += (long long)z * sB;
    const long long cbase = (long long)(z / zdiv) * sC1 + (long long)(z % zdiv) * sC2;
    const int row0 = blockIdx.y * 128, col0 = blockIdx.x * 128;

    float acc[4][4][4];
    #pragma unroll
    for (int a = 0; a < 4; a++)
        #pragma unroll
        for (int b = 0; b < 4; b++)
            #pragma unroll
            for (int c = 0; c < 4; c++) acc[a][b][c] = 0.0f;

    const int nk = K >> 5;   // K / 32; K is always a multiple of 32, nk >= 4

    auto issue = [&](int ch, int s) {
        const int k0 = ch << 5;
        const uint32_t Ab = sb + s * STAGE_B;
        const uint32_t Bb = Ab + STB;
        #pragma unroll
        for (int t = 0; t < 4; t++) {
            int idx = tid + t * 256;             // 0..1023
            int row = idx >> 3, cc = idx & 7;    // 128 rows x 8 chunks of 16B
            uint32_t da = Ab + (uint32_t)(row * 36 + cc * 4) * 4u;
            const float* pa = A + (long long)(row0 + row) * lda + k0 + cc * 4;
            asm volatile("cp.async.cg.shared.global [%0], [%1], 16;" :: "r"(da), "l"(pa));
            uint32_t db = Bb + (uint32_t)(row * 36 + cc * 4) * 4u;
            const float* pb = B + (long long)(col0 + row) * ldb + k0 + cc * 4;
            asm volatile("cp.async.cg.shared.global [%0], [%1], 16;" :: "r"(db), "l"(pb));
        }
    };

    #pragma unroll
    for (int s = 0; s < STAGES; s++) {
        issue(s, s);
        asm volatile("cp.async.commit_group;");
    }

    for (int i = 0; i < nk; i++) {
        const int s = i % STAGES;
        asm volatile("cp.async.wait_group %0;" :: "n"(STAGES - 1));
        __syncthreads();
        const float* As = sm + s * (STAGE_B / 4);
        const float* Bs = As + STF;

        #pragma unroll
        for (int kk = 0; kk < 32; kk += 8) {
            uint32_t af[4][4], bf[4][2];
            #pragma unroll
            for (int mt = 0; mt < 4; mt++) {
                int rm = wm * 64 + mt * 16 + (lane >> 2);
                const float* p0 = As + rm * 36 + kk + (lane & 3);
                af[mt][0] = f2tf32(p0[0]);
                af[mt][1] = f2tf32(p0[8 * 36]);
                af[mt][2] = f2tf32(p0[4]);
                af[mt][3] = f2tf32(p0[8 * 36 + 4]);
            }
            #pragma unroll
            for (int nt = 0; nt < 4; nt++) {
                int cn = wn * 32 + nt * 8 + (lane >> 2);
                const float* p0 = Bs + cn * 36 + kk + (lane & 3);
                bf[nt][0] = f2tf32(p0[0]);
                bf[nt][1] = f2tf32(p0[4]);
            }
            #pragma unroll
            for (int mt = 0; mt < 4; mt++)
                #pragma unroll
                for (int nt = 0; nt < 4; nt++)
                    asm volatile(
                        "mma.sync.aligned.m16n8k8.row.col.f32.tf32.tf32.f32 "
                        "{%0,%1,%2,%3}, {%4,%5,%6,%7}, {%8,%9}, {%0,%1,%2,%3};"
                        : "+f"(acc[mt][nt][0]), "+f"(acc[mt][nt][1]),
                          "+f"(acc[mt][nt][2]), "+f"(acc[mt][nt][3])
                        : "r"(af[mt][0]), "r"(af[mt][1]), "r"(af[mt][2]), "r"(af[mt][3]),
                          "r"(bf[nt][0]), "r"(bf[nt][1]));
        }
        __syncthreads();
        if (i + STAGES < nk) issue(i + STAGES, s);
        asm volatile("cp.async.commit_group;");
    }

    // epilogue: fragment layout c0:(r,c) c1:(r,c+1) c2:(r+8,c) c3:(r+8,c+1)
    #pragma unroll
    for (int mt = 0; mt < 4; mt++) {
        #pragma unroll
        for (int nt = 0; nt < 4; nt++) {
            int r_ = row0 + wm * 64 + mt * 16 + (lane >> 2);
            int c_ = col0 + wn * 32 + nt * 8 + (lane & 3) * 2;
            #pragma unroll
            for (int half = 0; half < 2; half++) {
                int r = r_ + half * 8;
                float v0 = acc[mt][nt][half * 2 + 0] + (bias ? bias[c_] : 0.0f);
                float v1 = acc[mt][nt][half * 2 + 1] + (bias ? bias[c_ + 1] : 0.0f);
                if (CMODE == 1) {
                    int b_ = r >> 11, s_ = r & 2047;
                    int h0 = c_ / headW, d0 = c_ % headW;
                    C[(((long long)(b_ * NH + h0)) * SEQ + s_) * DH + destOff + d0] = v0;
                    int h1 = (c_ + 1) / headW, d1 = (c_ + 1) % headW;
                    C[(((long long)(b_ * NH + h1)) * SEQ + s_) * DH + destOff + d1] = v1;
                } else {
                    float2 vv = make_float2(v0, v1);
                    *(float2*)&C[cbase + (long long)r * ldc + c_] = vv;
                }
            }
        }
    }
}

// ---------------- batched transpose: dst[N][K] = src[K][N] ------------------
__global__ void __launch_bounds__(256)
transpose_b(const float* __restrict__ src, float* __restrict__ dst,
            int K, int N, long long zs)
{
    __shared__ float t[32][33];
    src += (long long)blockIdx.z * zs;
    dst += (long long)blockIdx.z * zs;
    const int bn = blockIdx.x * 32, bk = blockIdx.y * 32;
    const int tx = threadIdx.x & 31, ty = threadIdx.x >> 5;  // 32x8
    #pragma unroll
    for (int j = 0; j < 4; j++)
        t[ty + 8 * j][tx] = src[(long long)(bk + ty + 8 * j) * N + bn + tx];
    __syncthreads();
    #pragma unroll
    for (int j = 0; j < 4; j++)
        dst[(long long)(bn + ty + 8 * j) * K + bk + tx] = t[tx][ty + 8 * j];
}

// ---------------- RoPE: rotate first 8 of 16 dims, scatter to dst[...,624:640]
__global__ void rope_scatter(const float* __restrict__ src, float* __restrict__ dst)
{
    int t = blockIdx.x * blockDim.x + threadIdx.x;
    if (t >= ROWS * NH) return;
    int r = t / NH, h = t % NH;
    int b_ = r / SEQ, s = r % SEQ;
    const float* x = src + (long long)r * (NH * 16) + h * 16;
    float* o = dst + (((long long)(b_ * NH + h)) * SEQ + s) * DH + SPLITD;

    float tpos = (float)s / 40.0f;
    #pragma unroll
    for (int j = 0; j < 4; j++) {
        float invf = powf(10000.0f, -0.25f * (float)j);
        float f = tpos * invf;
        float cs = cosf(f), sn = sinf(f);
        float x1 = x[j], x2 = x[j + 4];
        o[j]     = x1 * cs - x2 * sn;
        o[j + 4] = x2 * cs + x1 * sn;
    }
    #pragma unroll
    for (int j = 8; j < 16; j++) o[j] = x[j];
}

// ---------------- row softmax over 2048 cols (with 1/sqrt(640) scale) -------
__global__ void __launch_bounds__(256)
softmax_rows(float* __restrict__ sc)
{
    long long row = blockIdx.x;
    float* p = sc + row * SEQ;
    const float scale = rsqrtf(640.0f);
    int tid = threadIdx.x;
    __shared__ float red[256];

    float vals[8];
    float mx = -1e30f;
    #pragma unroll
    for (int i = 0; i < 8; i++) {
        vals[i] = p[tid + i * 256] * scale;
        mx = fmaxf(mx, vals[i]);
    }
    red[tid] = mx; __syncthreads();
    for (int s = 128; s > 0; s >>= 1) {
        if (tid < s) red[tid] = fmaxf(red[tid], red[tid + s]);
        __syncthreads();
    }
    mx = red[0]; __syncthreads();

    float sum = 0.0f;
    #pragma unroll
    for (int i = 0; i < 8; i++) { vals[i] = __expf(vals[i] - mx); sum += vals[i]; }
    red[tid] = sum; __syncthreads();
    for (int s = 128; s > 0; s >>= 1) {
        if (tid < s) red[tid] += red[tid + s];
        __syncthreads();
    }
    float inv = 1.0f / red[0];
    #pragma unroll
    for (int i = 0; i < 8; i++) p[tid + i * 256] = vals[i] * inv;
}

// ---------------- launch ----------------------------------------------------
extern "C" void kernel_launch(void* const* d_in, const int* in_sizes, int n_in,
                              void* d_out, int out_size)
{
    const float* h     = (const float*)d_in[0];
    const float* W_dkv = (const float*)d_in[1];
    const float* b_dkv = (const float*)d_in[2];
    const float* W_dq  = (const float*)d_in[3];
    const float* b_dq  = (const float*)d_in[4];
    const float* W_uk  = (const float*)d_in[5];
    const float* b_uk  = (const float*)d_in[6];
    const float* W_uv  = (const float*)d_in[7];
    const float* b_uv  = (const float*)d_in[8];
    const float* W_uq  = (const float*)d_in[9];
    const float* b_uq  = (const float*)d_in[10];
    const float* W_qr  = (const float*)d_in[11];
    const float* b_qr  = (const float*)d_in[12];
    const float* W_kr  = (const float*)d_in[13];
    const float* b_kr  = (const float*)d_in[14];
    const float* W_o   = (const float*)d_in[15];
    const float* b_o   = (const float*)d_in[16];
    float* out = (float*)d_out;

    float *ckv, *cq, *kr, *qr, *q, *k, *v, *vT, *sc, *ao;
    float *WdkvT, *WdqT, *WkrT, *WukT, *WuvT, *WuqT, *WqrT, *WoT;
    cudaGetSymbolAddress((void**)&ckv,  g_ckv);
    cudaGetSymbolAddress((void**)&cq,   g_cq);
    cudaGetSymbolAddress((void**)&kr,   g_kr);
    cudaGetSymbolAddress((void**)&qr,   g_qr);
    cudaGetSymbolAddress((void**)&q,    g_q);
    cudaGetSymbolAddress((void**)&k,    g_k);
    cudaGetSymbolAddress((void**)&v,    g_v);
    cudaGetSymbolAddress((void**)&vT,   g_vT);
    cudaGetSymbolAddress((void**)&sc,   g_sc);
    cudaGetSymbolAddress((void**)&ao,   g_ao);
    cudaGetSymbolAddress((void**)&WdkvT, g_WdkvT);
    cudaGetSymbolAddress((void**)&WdqT,  g_WdqT);
    cudaGetSymbolAddress((void**)&WkrT,  g_WkrT);
    cudaGetSymbolAddress((void**)&WukT,  g_WukT);
    cudaGetSymbolAddress((void**)&WuvT,  g_WuvT);
    cudaGetSymbolAddress((void**)&WuqT,  g_WuqT);
    cudaGetSymbolAddress((void**)&WqrT,  g_WqrT);
    cudaGetSymbolAddress((void**)&WoT,   g_WoT);

    cudaFuncSetAttribute(mma_gemm<0>, cudaFuncAttributeMaxDynamicSharedMemorySize, SMEMB);
    cudaFuncSetAttribute(mma_gemm<1>, cudaFuncAttributeMaxDynamicSharedMemorySize, SMEMB);

    // weight transposes: dst[N][K] = src[K][N]
    transpose_b<<<dim3(DKV/32, DM/32, 1), 256>>>(W_dkv, WdkvT, DM, DKV, 0);
    transpose_b<<<dim3(DKV/32, DM/32, 1), 256>>>(W_dq,  WdqT,  DM, DKV, 0);
    transpose_b<<<dim3(128/32, DM/32, 1), 256>>>(W_kr,  WkrT,  DM, 128, 0);
    transpose_b<<<dim3((NH*SPLITD)/32, DKV/32, 1), 256>>>(W_uk, WukT, DKV, NH*SPLITD, 0);
    transpose_b<<<dim3((NH*DH)/32,     DKV/32, 1), 256>>>(W_uv, WuvT, DKV, NH*DH, 0);
    transpose_b<<<dim3((NH*SPLITD)/32, DKV/32, 1), 256>>>(W_uq, WuqT, DKV, NH*SPLITD, 0);
    transpose_b<<<dim3(128/32,         DKV/32, 1), 256>>>(W_qr, WqrT, DKV, 128, 0);
    transpose_b<<<dim3(DM/32, DM/32, 1),  256>>>(W_o, WoT, DM, DM, 0);

    const long long Z = 0;

    // 1) down-projections: [4096,5120] x [5120,128]
    mma_gemm<0><<<dim3(1,32,1),256,SMEMB>>>(h, WdkvT, b_dkv, ckv,
        DM, DM, DM, 128, Z,Z,Z,Z,1, 0,0);
    mma_gemm<0><<<dim3(1,32,1),256,SMEMB>>>(h, WdqT, b_dq, cq,
        DM, DM, DM, 128, Z,Z,Z,Z,1, 0,0);
    mma_gemm<0><<<dim3(1,32,1),256,SMEMB>>>(h, WkrT, b_kr, kr,
        DM, DM, DM, 128, Z,Z,Z,Z,1, 0,0);

    // 2) up-projections (scatter into head layouts)
    mma_gemm<1><<<dim3(39,32,1),256,SMEMB>>>(ckv, WukT, b_uk, k,
        DKV, DKV, DKV, 0, Z,Z,Z,Z,1, SPLITD,0);
    mma_gemm<1><<<dim3(40,32,1),256,SMEMB>>>(ckv, WuvT, b_uv, v,
        DKV, DKV, DKV, 0, Z,Z,Z,Z,1, DH,0);
    mma_gemm<1><<<dim3(39,32,1),256,SMEMB>>>(cq, WuqT, b_uq, q,
        DKV, DKV, DKV, 0, Z,Z,Z,Z,1, SPLITD,0);
    mma_gemm<0><<<dim3(1,32,1),256,SMEMB>>>(cq, WqrT, b_qr, qr,
        DKV, DKV, DKV, 128, Z,Z,Z,Z,1, 0,0);

    // 3) RoPE scatter into q/k [...,624:640]
    rope_scatter<<<(ROWS*NH + 255)/256, 256>>>(qr, q);
    rope_scatter<<<(ROWS*NH + 255)/256, 256>>>(kr, k);

    // 3b) per-head transpose of v: [bh][s][640] -> vT [bh][d][s]
    transpose_b<<<dim3(DH/32, SEQ/32, NB*NH), 256>>>(v, vT, SEQ, DH, (long long)SEQ*DH);

    // 4) scores = q @ k^T per head (z = bh); scale applied in softmax
    mma_gemm<0><<<dim3(16,16,16),256,SMEMB>>>(q, k, nullptr, sc,
        DH, DH, DH, SEQ,
        (long long)SEQ*DH, (long long)SEQ*DH, Z, (long long)SEQ*SEQ, 16, 0,0);

    // 5) softmax
    softmax_rows<<<NB*NH*SEQ, 256>>>(sc);

    // 6) attn @ v (B = vT, K-major [640][2048]) -> ao[b][s][h*640]
    mma_gemm<0><<<dim3(5,16,16),256,SMEMB>>>(sc, vT, nullptr, ao,
        SEQ, SEQ, SEQ, DM,
        (long long)SEQ*SEQ, (long long)DH*SEQ,
        (long long)SEQ*DM, (long long)DH, NH, 0,0);

    // 7) final: [4096,5120] x [5120,5120] + b_o
    mma_gemm<0><<<dim3(40,32,1),256,SMEMB>>>(ao, WoT, b_o, out,
        DM, DM, DM, DM, Z,Z,Z,Z,1, 0,0);
}

// round 5
// speedup vs baseline: 4.5818x; 1.8854x over previous
#include <cuda_runtime.h>
#include <cstdint>

#define SEQ   2048
#define NH    8
#define DH    640
#define DKV   128
#define NB    2
#define ROWS  (NB*SEQ)     // 4096
#define DM    5120
#define SPLITD 624
#define STAGES 3
// 128x128 kernel smem
#define STF   (128*36)
#define STB   (STF*4)
#define STAGE_B (2*STB)          // 36864 B
#define SMEMB (STAGES*STAGE_B)   // 110592 B
// 256x128 kernel smem
#define STF_A2 (256*36)
#define STF_B2 (128*36)
#define STAGE_F2 (STF_A2+STF_B2)       // 13824 floats
#define STAGE_B2 (STAGE_F2*4)          // 55296 B
#define SMEMB2 (STAGES*STAGE_B2)       // 165888 B

// ---------------- scratch (device globals; allocation-free) ----------------
__device__ float g_hr  [(size_t)ROWS*DM];         // tf32-rounded h
__device__ float g_cdown[ROWS*384];               // [ckv | cq | kr]
__device__ float g_bdown[384];
__device__ float g_qr [ROWS*DKV];
__device__ float g_q  [(size_t)NB*NH*SEQ*DH];     // [bh][s][640]
__device__ float g_k  [(size_t)NB*NH*SEQ*DH];     // [bh][s][640]
__device__ float g_vT [(size_t)NB*NH*DH*SEQ];     // [bh][d][s]
__device__ float g_sc [(size_t)NB*NH*SEQ*SEQ];    // [bh][s][s]
__device__ float g_ao [(size_t)ROWS*DM];          // [b][s][h*640]
// transposed weights (stored [N][K], K-major), tf32-rounded
__device__ float g_WdownT[384*DM];                // [W_dkv^T | W_dq^T | W_kr^T]
__device__ float g_WukT [(NH*SPLITD)*DKV];
__device__ float g_WuvT [(NH*DH)*DKV];
__device__ float g_WuqT [(NH*SPLITD)*DKV];
__device__ float g_WqrT [(NH*16)*DKV];
__device__ float g_WoT  [(size_t)DM*DM];

// ---------------- helpers ---------------------------------------------------
__device__ __forceinline__ uint32_t smem_u32(const void* p) {
    uint32_t a;
    asm("{ .reg .u64 t; cvta.to.shared.u64 t, %1; cvt.u32.u64 %0, t; }"
        : "=r"(a) : "l"(p));
    return a;
}
__device__ __forceinline__ float roundtf(float x) {
    uint32_t u;
    asm("cvt.rna.tf32.f32 %0, %1;" : "=r"(u) : "f"(x));
    return __uint_as_float(u);
}

#define MMA_TF32(acc, af, bf) \
    asm volatile( \
        "mma.sync.aligned.m16n8k8.row.col.f32.tf32.tf32.f32 " \
        "{%0,%1,%2,%3}, {%4,%5,%6,%7}, {%8,%9}, {%0,%1,%2,%3};" \
        : "+f"((acc)[0]), "+f"((acc)[1]), "+f"((acc)[2]), "+f"((acc)[3]) \
        : "r"((af)[0]), "r"((af)[1]), "r"((af)[2]), "r"((af)[3]), \
          "r"((bf)[0]), "r"((bf)[1]))

// ---------------- 128x128 tf32 GEMM: C = A[M,K] @ B[N,K]^T (+bias) ----------
// CMODE 0: C[r*ldc + c]
// CMODE 1: headmap: C[((b*NH+h)*SEQ+s)*640 + destOff + d], h=c/headW, d=c%headW
// CMODE 2: headmap transposed (vT): C[((b*NH+h)*DH + d)*SEQ + s], headW=DH
// RND: round outputs to tf32-representable
template<int CMODE, int RND>
__global__ void __launch_bounds__(256, 1)
gemm128(const float* __restrict__ A, const float* __restrict__ B,
        const float* __restrict__ bias, float* __restrict__ C,
        int K, int lda, int ldb, int ldc, int headW, int destOff)
{
    extern __shared__ float sm[];
    const uint32_t sb = smem_u32(sm);
    const int tid = threadIdx.x, lane = tid & 31, wid = tid >> 5;
    const int wm = wid >> 2, wn = wid & 3;       // 2 (m) x 4 (n), warp 64x32
    const int row0 = blockIdx.y * 128, col0 = blockIdx.x * 128;

    float acc[4][4][4];
    #pragma unroll
    for (int a = 0; a < 4; a++)
        #pragma unroll
        for (int b = 0; b < 4; b++)
            #pragma unroll
            for (int c = 0; c < 4; c++) acc[a][b][c] = 0.0f;

    const int nk = K >> 5;

    auto issue = [&](int ch, int s) {
        const int k0 = ch << 5;
        const uint32_t Ab = sb + s * STAGE_B;
        const uint32_t Bb = Ab + STB;
        #pragma unroll
        for (int t = 0; t < 4; t++) {
            int idx = tid + t * 256;
            int row = idx >> 3, cc = idx & 7;
            uint32_t da = Ab + (uint32_t)(row * 36 + cc * 4) * 4u;
            const float* pa = A + (long long)(row0 + row) * lda + k0 + cc * 4;
            asm volatile("cp.async.cg.shared.global [%0], [%1], 16;" :: "r"(da), "l"(pa));
            uint32_t db = Bb + (uint32_t)(row * 36 + cc * 4) * 4u;
            const float* pb = B + (long long)(col0 + row) * ldb + k0 + cc * 4;
            asm volatile("cp.async.cg.shared.global [%0], [%1], 16;" :: "r"(db), "l"(pb));
        }
    };

    #pragma unroll
    for (int s = 0; s < STAGES; s++) {
        issue(s, s);
        asm volatile("cp.async.commit_group;");
    }

    for (int i = 0; i < nk; i++) {
        const int s = i % STAGES;
        asm volatile("cp.async.wait_group %0;" :: "n"(STAGES - 1));
        __syncthreads();
        const uint32_t* As = (const uint32_t*)(sm + s * (STAGE_B / 4));
        const uint32_t* Bs = As + STF;

        #pragma unroll
        for (int kk = 0; kk < 32; kk += 8) {
            uint32_t af[4][4], bf[4][2];
            #pragma unroll
            for (int mt = 0; mt < 4; mt++) {
                int rm = wm * 64 + mt * 16 + (lane >> 2);
                const uint32_t* p0 = As + rm * 36 + kk + (lane & 3);
                af[mt][0] = p0[0];
                af[mt][1] = p0[8 * 36];
                af[mt][2] = p0[4];
                af[mt][3] = p0[8 * 36 + 4];
            }
            #pragma unroll
            for (int nt = 0; nt < 4; nt++) {
                int cn = wn * 32 + nt * 8 + (lane >> 2);
                const uint32_t* p0 = Bs + cn * 36 + kk + (lane & 3);
                bf[nt][0] = p0[0];
                bf[nt][1] = p0[4];
            }
            #pragma unroll
            for (int mt = 0; mt < 4; mt++)
                #pragma unroll
                for (int nt = 0; nt < 4; nt++)
                    MMA_TF32(acc[mt][nt], af[mt], bf[nt]);
        }
        __syncthreads();
        if (i + STAGES < nk) issue(i + STAGES, s);
        asm volatile("cp.async.commit_group;");
    }

    #pragma unroll
    for (int mt = 0; mt < 4; mt++) {
        #pragma unroll
        for (int nt = 0; nt < 4; nt++) {
            int r_ = row0 + wm * 64 + mt * 16 + (lane >> 2);
            int c_ = col0 + wn * 32 + nt * 8 + (lane & 3) * 2;
            #pragma unroll
            for (int half = 0; half < 2; half++) {
                int r = r_ + half * 8;
                float v0 = acc[mt][nt][half * 2 + 0] + (bias ? bias[c_] : 0.0f);
                float v1 = acc[mt][nt][half * 2 + 1] + (bias ? bias[c_ + 1] : 0.0f);
                if (RND) { v0 = roundtf(v0); v1 = roundtf(v1); }
                if (CMODE == 1) {
                    int b_ = r >> 11, s_ = r & 2047;
                    int h0 = c_ / headW, d0 = c_ % headW;
                    C[(((long long)(b_ * NH + h0)) * SEQ + s_) * DH + destOff + d0] = v0;
                    int h1 = (c_ + 1) / headW, d1 = (c_ + 1) % headW;
                    C[(((long long)(b_ * NH + h1)) * SEQ + s_) * DH + destOff + d1] = v1;
                } else if (CMODE == 2) {
                    int b_ = r >> 11, s_ = r & 2047;
                    int h0 = c_ / DH, d0 = c_ % DH;
                    C[(((long long)(b_ * NH + h0)) * DH + d0) * SEQ + s_] = v0;
                    int h1 = (c_ + 1) / DH, d1 = (c_ + 1) % DH;
                    C[(((long long)(b_ * NH + h1)) * DH + d1) * SEQ + s_] = v1;
                } else {
                    *(float2*)&C[(long long)r * ldc + c_] = make_float2(v0, v1);
                }
            }
        }
    }
}

// ---------------- 256x128 tf32 GEMM (batched over z), CMODE0 only -----------
template<int RND>
__global__ void __launch_bounds__(256, 1)
gemm256(const float* __restrict__ A, const float* __restrict__ B,
        const float* __restrict__ bias, float* __restrict__ C,
        int K, int lda, int ldb, int ldc,
        long long sA, long long sB, long long sC1, long long sC2, int zdiv)
{
    extern __shared__ float sm[];
    const uint32_t sb = smem_u32(sm);
    const int tid = threadIdx.x, lane = tid & 31, wid = tid >> 5;
    const int wm = wid >> 1, wn = wid & 1;       // 4 (m) x 2 (n), warp 64x64
    const int z = blockIdx.z;
    A += (long long)z * sA;
    B += (long long)z * sB;
    const long long cbase = (long long)(z / zdiv) * sC1 + (long long)(z % zdiv) * sC2;
    const int row0 = blockIdx.y * 256, col0 = blockIdx.x * 128;

    float acc[4][8][4];
    #pragma unroll
    for (int a = 0; a < 4; a++)
        #pragma unroll
        for (int b = 0; b < 8; b++)
            #pragma unroll
            for (int c = 0; c < 4; c++) acc[a][b][c] = 0.0f;

    const int nk = K >> 5;

    auto issue = [&](int ch, int s) {
        const int k0 = ch << 5;
        const uint32_t Ab = sb + s * STAGE_B2;
        const uint32_t Bb = Ab + STF_A2 * 4;
        #pragma unroll
        for (int t = 0; t < 8; t++) {           // A: 256 rows
            int idx = tid + t * 256;
            int row = idx >> 3, cc = idx & 7;
            uint32_t da = Ab + (uint32_t)(row * 36 + cc * 4) * 4u;
            const float* pa = A + (long long)(row0 + row) * lda + k0 + cc * 4;
            asm volatile("cp.async.cg.shared.global [%0], [%1], 16;" :: "r"(da), "l"(pa));
        }
        #pragma unroll
        for (int t = 0; t < 4; t++) {           // B: 128 rows
            int idx = tid + t * 256;
            int row = idx >> 3, cc = idx & 7;
            uint32_t db = Bb + (uint32_t)(row * 36 + cc * 4) * 4u;
            const float* pb = B + (long long)(col0 + row) * ldb + k0 + cc * 4;
            asm volatile("cp.async.cg.shared.global [%0], [%1], 16;" :: "r"(db), "l"(pb));
        }
    };

    #pragma unroll
    for (int s = 0; s < STAGES; s++) {
        issue(s, s);
        asm volatile("cp.async.commit_group;");
    }

    for (int i = 0; i < nk; i++) {
        const int s = i % STAGES;
        asm volatile("cp.async.wait_group %0;" :: "n"(STAGES - 1));
        __syncthreads();
        const uint32_t* As = (const uint32_t*)(sm + s * STAGE_F2);
        const uint32_t* Bs = As + STF_A2;

        #pragma unroll
        for (int kk = 0; kk < 32; kk += 8) {
            uint32_t af[4][4], bf[8][2];
            #pragma unroll
            for (int mt = 0; mt < 4; mt++) {
                int rm = wm * 64 + mt * 16 + (lane >> 2);
                const uint32_t* p0 = As + rm * 36 + kk + (lane & 3);
                af[mt][0] = p0[0];
                af[mt][1] = p0[8 * 36];
                af[mt][2] = p0[4];
                af[mt][3] = p0[8 * 36 + 4];
            }
            #pragma unroll
            for (int nt = 0; nt < 8; nt++) {
                int cn = wn * 64 + nt * 8 + (lane >> 2);
                const uint32_t* p0 = Bs + cn * 36 + kk + (lane & 3);
                bf[nt][0] = p0[0];
                bf[nt][1] = p0[4];
            }
            #pragma unroll
            for (int mt = 0; mt < 4; mt++)
                #pragma unroll
                for (int nt = 0; nt < 8; nt++)
                    MMA_TF32(acc[mt][nt], af[mt], bf[nt]);
        }
        __syncthreads();
        if (i + STAGES < nk) issue(i + STAGES, s);
        asm volatile("cp.async.commit_group;");
    }

    #pragma unroll
    for (int mt = 0; mt < 4; mt++) {
        #pragma unroll
        for (int nt = 0; nt < 8; nt++) {
            int r_ = row0 + wm * 64 + mt * 16 + (lane >> 2);
            int c_ = col0 + wn * 64 + nt * 8 + (lane & 3) * 2;
            #pragma unroll
            for (int half = 0; half < 2; half++) {
                int r = r_ + half * 8;
                float v0 = acc[mt][nt][half * 2 + 0] + (bias ? bias[c_] : 0.0f);
                float v1 = acc[mt][nt][half * 2 + 1] + (bias ? bias[c_ + 1] : 0.0f);
                if (RND) { v0 = roundtf(v0); v1 = roundtf(v1); }
                *(float2*)&C[cbase + (long long)r * ldc + c_] = make_float2(v0, v1);
            }
        }
    }
}

// ---------------- transpose (+tf32 round): dst[N][K] = src[K][N] ------------
__global__ void __launch_bounds__(256)
transpose_r(const float* __restrict__ src, float* __restrict__ dst, int K, int N)
{
    __shared__ float t[32][33];
    const int bn = blockIdx.x * 32, bk = blockIdx.y * 32;
    const int tx = threadIdx.x & 31, ty = threadIdx.x >> 5;
    #pragma unroll
    for (int j = 0; j < 4; j++)
        t[ty + 8 * j][tx] = src[(long long)(bk + ty + 8 * j) * N + bn + tx];
    __syncthreads();
    #pragma unroll
    for (int j = 0; j < 4; j++)
        dst[(long long)(bn + ty + 8 * j) * K + bk + tx] = roundtf(t[tx][ty + 8 * j]);
}

// ---------------- tf32 rounding pass (h -> hr), float4 ----------------------
__global__ void round_pass(const float* __restrict__ src, float* __restrict__ dst,
                           long long n4)
{
    long long i = (long long)blockIdx.x * blockDim.x + threadIdx.x;
    if (i >= n4) return;
    float4 v = ((const float4*)src)[i];
    v.x = roundtf(v.x); v.y = roundtf(v.y); v.z = roundtf(v.z); v.w = roundtf(v.w);
    ((float4*)dst)[i] = v;
}

// ---------------- bias gather for fused down-proj ---------------------------
__global__ void gather_bias(const float* b0, const float* b1, const float* b2,
                            float* dst)
{
    int i = threadIdx.x + blockIdx.x * blockDim.x;
    if (i >= 384) return;
    dst[i] = (i < 128) ? b0[i] : (i < 256) ? b1[i - 128] : b2[i - 256];
}

// ---------------- RoPE: rotate first 8 of 16 dims, scatter to dst[...,624:640]
__global__ void rope_scatter(const float* __restrict__ src, int sstride,
                             float* __restrict__ dst)
{
    int t = blockIdx.x * blockDim.x + threadIdx.x;
    if (t >= ROWS * NH) return;
    int r = t / NH, h = t % NH;
    int b_ = r / SEQ, s = r % SEQ;
    const float* x = src + (long long)r * sstride + h * 16;
    float* o = dst + (((long long)(b_ * NH + h)) * SEQ + s) * DH + SPLITD;

    float tpos = (float)s / 40.0f;
    #pragma unroll
    for (int j = 0; j < 4; j++) {
        float invf = powf(10000.0f, -0.25f * (float)j);
        float f = tpos * invf;
        float cs = cosf(f), sn = sinf(f);
        float x1 = x[j], x2 = x[j + 4];
        o[j]     = roundtf(x1 * cs - x2 * sn);
        o[j + 4] = roundtf(x2 * cs + x1 * sn);
    }
    #pragma unroll
    for (int j = 8; j < 16; j++) o[j] = roundtf(x[j]);
}

// ---------------- row softmax over 2048 cols (+tf32 round) ------------------
__global__ void __launch_bounds__(256)
softmax_rows(float* __restrict__ sc)
{
    long long row = blockIdx.x;
    float* p = sc + row * SEQ;
    const float scale = rsqrtf(640.0f);
    int tid = threadIdx.x;
    __shared__ float red[256];

    float vals[8];
    float mx = -1e30f;
    #pragma unroll
    for (int i = 0; i < 8; i++) {
        vals[i] = p[tid + i * 256] * scale;
        mx = fmaxf(mx, vals[i]);
    }
    red[tid] = mx; __syncthreads();
    for (int s = 128; s > 0; s >>= 1) {
        if (tid < s) red[tid] = fmaxf(red[tid], red[tid + s]);
        __syncthreads();
    }
    mx = red[0]; __syncthreads();

    float sum = 0.0f;
    #pragma unroll
    for (int i = 0; i < 8; i++) { vals[i] = __expf(vals[i] - mx); sum += vals[i]; }
    red[tid] = sum; __syncthreads();
    for (int s = 128; s > 0; s >>= 1) {
        if (tid < s) red[tid] += red[tid + s];
        __syncthreads();
    }
    float inv = 1.0f / red[0];
    #pragma unroll
    for (int i = 0; i < 8; i++) p[tid + i * 256] = roundtf(vals[i] * inv);
}

// ---------------- launch ----------------------------------------------------
extern "C" void kernel_launch(void* const* d_in, const int* in_sizes, int n_in,
                              void* d_out, int out_size)
{
    const float* h     = (const float*)d_in[0];
    const float* W_dkv = (const float*)d_in[1];
    const float* b_dkv = (const float*)d_in[2];
    const float* W_dq  = (const float*)d_in[3];
    const float* b_dq  = (const float*)d_in[4];
    const float* W_uk  = (const float*)d_in[5];
    const float* b_uk  = (const float*)d_in[6];
    const float* W_uv  = (const float*)d_in[7];
    const float* b_uv  = (const float*)d_in[8];
    const float* W_uq  = (const float*)d_in[9];
    const float* b_uq  = (const float*)d_in[10];
    const float* W_qr  = (const float*)d_in[11];
    const float* b_qr  = (const float*)d_in[12];
    const float* W_kr  = (const float*)d_in[13];
    const float* b_kr  = (const float*)d_in[14];
    const float* W_o   = (const float*)d_in[15];
    const float* b_o   = (const float*)d_in[16];
    float* out = (float*)d_out;

    float *hr, *cdown, *bdown, *qr, *q, *k, *vT, *sc, *ao;
    float *WdownT, *WukT, *WuvT, *WuqT, *WqrT, *WoT;
    cudaGetSymbolAddress((void**)&hr,    g_hr);
    cudaGetSymbolAddress((void**)&cdown, g_cdown);
    cudaGetSymbolAddress((void**)&bdown, g_bdown);
    cudaGetSymbolAddress((void**)&qr,    g_qr);
    cudaGetSymbolAddress((void**)&q,     g_q);
    cudaGetSymbolAddress((void**)&k,     g_k);
    cudaGetSymbolAddress((void**)&vT,    g_vT);
    cudaGetSymbolAddress((void**)&sc,    g_sc);
    cudaGetSymbolAddress((void**)&ao,    g_ao);
    cudaGetSymbolAddress((void**)&WdownT, g_WdownT);
    cudaGetSymbolAddress((void**)&WukT,  g_WukT);
    cudaGetSymbolAddress((void**)&WuvT,  g_WuvT);
    cudaGetSymbolAddress((void**)&WuqT,  g_WuqT);
    cudaGetSymbolAddress((void**)&WqrT,  g_WqrT);
    cudaGetSymbolAddress((void**)&WoT,   g_WoT);

    cudaFuncSetAttribute(gemm128<0,0>, cudaFuncAttributeMaxDynamicSharedMemorySize, SMEMB);
    cudaFuncSetAttribute(gemm128<0,1>, cudaFuncAttributeMaxDynamicSharedMemorySize, SMEMB);
    cudaFuncSetAttribute(gemm128<1,1>, cudaFuncAttributeMaxDynamicSharedMemorySize, SMEMB);
    cudaFuncSetAttribute(gemm128<2,1>, cudaFuncAttributeMaxDynamicSharedMemorySize, SMEMB);
    cudaFuncSetAttribute(gemm256<0>, cudaFuncAttributeMaxDynamicSharedMemorySize, SMEMB2);
    cudaFuncSetAttribute(gemm256<1>, cudaFuncAttributeMaxDynamicSharedMemorySize, SMEMB2);

    // 0) round h -> hr
    {
        long long n4 = (long long)ROWS * DM / 4;
        round_pass<<<(unsigned)((n4 + 255) / 256), 256>>>(h, hr, n4);
    }

    // weight transposes (+round): dst[N][K] = src[K][N]
    transpose_r<<<dim3(DKV/32, DM/32), 256>>>(W_dkv, WdownT,            DM, DKV);
    transpose_r<<<dim3(DKV/32, DM/32), 256>>>(W_dq,  WdownT + 128*DM,   DM, DKV);
    transpose_r<<<dim3(128/32, DM/32), 256>>>(W_kr,  WdownT + 256*DM,   DM, 128);
    transpose_r<<<dim3((NH*SPLITD)/32, DKV/32), 256>>>(W_uk, WukT, DKV, NH*SPLITD);
    transpose_r<<<dim3((NH*DH)/32,     DKV/32), 256>>>(W_uv, WuvT, DKV, NH*DH);
    transpose_r<<<dim3((NH*SPLITD)/32, DKV/32), 256>>>(W_uq, WuqT, DKV, NH*SPLITD);
    transpose_r<<<dim3(128/32,         DKV/32), 256>>>(W_qr, WqrT, DKV, 128);
    transpose_r<<<dim3(DM/32, DM/32),  256>>>(W_o, WoT, DM, DM);
    gather_bias<<<2, 192>>>(b_dkv, b_dq, b_kr, bdown);

    // 1) fused down-projections: [4096,5120] x [5120,384] -> cdown
    gemm128<0,1><<<dim3(3,32),256,SMEMB>>>(hr, WdownT, bdown, cdown,
        DM, DM, DM, 384, 0,0);

    // 2) up-projections
    gemm128<1,1><<<dim3(39,32),256,SMEMB>>>(cdown, WukT, b_uk, k,
        DKV, 384, DKV, 0, SPLITD,0);
    gemm128<2,1><<<dim3(40,32),256,SMEMB>>>(cdown, WuvT, b_uv, vT,
        DKV, 384, DKV, 0, DH,0);
    gemm128<1,1><<<dim3(39,32),256,SMEMB>>>(cdown + 128, WuqT, b_uq, q,
        DKV, 384, DKV, 0, SPLITD,0);
    gemm128<0,1><<<dim3(1,32),256,SMEMB>>>(cdown + 128, WqrT, b_qr, qr,
        DKV, 384, DKV, 128, 0,0);

    // 3) RoPE scatter into q/k [...,624:640]
    rope_scatter<<<(ROWS*NH + 255)/256, 256>>>(qr, 128, q);
    rope_scatter<<<(ROWS*NH + 255)/256, 256>>>(cdown + 256, 384, k);

    // 4) scores = q @ k^T per head (z = bh); softmax applies scale + round
    gemm256<0><<<dim3(16,8,16),256,SMEMB2>>>(q, k, nullptr, sc,
        DH, DH, DH, SEQ,
        (long long)SEQ*DH, (long long)SEQ*DH, 0LL, (long long)SEQ*SEQ, 16);

    // 5) softmax (+round)
    softmax_rows<<<NB*NH*SEQ, 256>>>(sc);

    // 6) attn @ v (B = vT, K-major [640][2048]) -> ao[b][s][h*640] (+round)
    gemm256<1><<<dim3(5,8,16),256,SMEMB2>>>(sc, vT, nullptr, ao,
        SEQ, SEQ, SEQ, DM,
        (long long)SEQ*SEQ, (long long)DH*SEQ,
        (long long)SEQ*DM, (long long)DH, NH);

    // 7) final: [4096,5120] x [5120,5120] + b_o (no round)
    gemm256<0><<<dim3(40,16,1),256,SMEMB2>>>(ao, WoT, b_o, out,
        DM, DM, DM, DM, 0LL,0LL,0LL,0LL,1);
}

// round 6
// speedup vs baseline: 8.2634x; 1.8035x over previous
#include <cuda_runtime.h>
#include <cuda_fp16.h>
#include <cstdint>

#define SEQ   2048
#define NH    8
#define DH    640
#define DKV   128
#define NB    2
#define ROWS  (NB*SEQ)     // 4096
#define DM    5120
#define SPLITD 624
#define STAGES 3
// 128x128 fp16 kernel: KC=32 halves, stride 40 halves
#define S1    40
#define ST1F  (128*S1)               // halves per tile
#define STAGE1 (2*ST1F*2)            // bytes per stage (A+B) = 20480
#define SMEM1 (STAGES*STAGE1)        // 61440
// 256x128 fp16 kernel: KC=64 halves, stride 72 halves
#define S2    72
#define STAGE2 ((256+128)*S2*2)      // 55296
#define SMEM2 (STAGES*STAGE2)        // 165888

// ---------------- scratch (device globals; allocation-free) ----------------
__device__ __half g_hh  [(size_t)ROWS*DM];          // half h
__device__ __half g_cdown[ROWS*384];                // [ckv | cq | kr] half
__device__ float  g_bdown[384];
__device__ __half g_qr [ROWS*DKV];
__device__ __half g_q  [(size_t)NB*NH*SEQ*DH];      // [bh][s][640]
__device__ __half g_k  [(size_t)NB*NH*SEQ*DH];      // [bh][s][640]
__device__ __half g_vT [(size_t)NB*NH*DH*SEQ];      // [bh][d][s]
__device__ float  g_sc [(size_t)NB*NH*SEQ*SEQ];     // fp32 scores
__device__ __half g_at [(size_t)NB*NH*SEQ*SEQ];     // half attn
__device__ __half g_ao [(size_t)ROWS*DM];           // [b][s][h*640]
// transposed weights ([N][K] K-major, half)
__device__ __half g_WdownT[384*DM];                 // [W_dkv^T | W_dq^T | W_kr^T]
__device__ __half g_WukT [(NH*SPLITD)*DKV];
__device__ __half g_WuvT [(NH*DH)*DKV];
__device__ __half g_WuqT [(NH*SPLITD)*DKV];
__device__ __half g_WqrT [(NH*16)*DKV];
__device__ __half g_WoT  [(size_t)DM*DM];

// ---------------- helpers ---------------------------------------------------
__device__ __forceinline__ uint32_t smem_u32(const void* p) {
    uint32_t a;
    asm("{ .reg .u64 t; cvta.to.shared.u64 t, %1; cvt.u32.u64 %0, t; }"
        : "=r"(a) : "l"(p));
    return a;
}

#define MMA_F16(acc, af, bf) \
    asm volatile( \
        "mma.sync.aligned.m16n8k16.row.col.f32.f16.f16.f32 " \
        "{%0,%1,%2,%3}, {%4,%5,%6,%7}, {%8,%9}, {%0,%1,%2,%3};" \
        : "+f"((acc)[0]), "+f"((acc)[1]), "+f"((acc)[2]), "+f"((acc)[3]) \
        : "r"((af)[0]), "r"((af)[1]), "r"((af)[2]), "r"((af)[3]), \
          "r"((bf)[0]), "r"((bf)[1]))

__device__ __forceinline__ void st_pair(float* p, float a, float b) {
    *(float2*)p = make_float2(a, b);
}
__device__ __forceinline__ void st_pair(__half* p, float a, float b) {
    *(__half2*)p = __floats2half2_rn(a, b);
}
__device__ __forceinline__ void st_one(float* p, float a) { *p = a; }
__device__ __forceinline__ void st_one(__half* p, float a) { *p = __float2half_rn(a); }

// ---------------- 128x128 fp16 GEMM: C = A[M,K] @ B[N,K]^T (+bias) ----------
// CMODE 0: C[r*ldc + c]
// CMODE 1: headmap: C[((b*NH+h)*SEQ+s)*640 + destOff + d], h=c/headW, d=c%headW
// CMODE 2: headmap transposed (vT): C[((b*NH+h)*DH + d)*SEQ + s]
template<int CMODE, typename OUTT>
__global__ void __launch_bounds__(256, 1)
gemm128h(const __half* __restrict__ A, const __half* __restrict__ B,
         const float* __restrict__ bias, OUTT* __restrict__ C,
         int K, int lda, int ldb, int ldc, int headW, int destOff)
{
    extern __shared__ __half smh[];
    const uint32_t sb = smem_u32(smh);
    const int tid = threadIdx.x, lane = tid & 31, wid = tid >> 5;
    const int wm = wid >> 2, wn = wid & 3;       // 2 (m) x 4 (n), warp 64x32
    const int row0 = blockIdx.y * 128, col0 = blockIdx.x * 128;

    float acc[4][4][4];
    #pragma unroll
    for (int a = 0; a < 4; a++)
        #pragma unroll
        for (int b = 0; b < 4; b++)
            #pragma unroll
            for (int c = 0; c < 4; c++) acc[a][b][c] = 0.0f;

    const int nk = K >> 5;   // KC = 32 halves

    auto issue = [&](int ch, int s) {
        const int k0 = ch << 5;
        const uint32_t Ab = sb + s * STAGE1;
        const uint32_t Bb = Ab + ST1F * 2;
        #pragma unroll
        for (int t = 0; t < 2; t++) {
            int idx = tid + t * 256;             // 0..511
            int row = idx >> 2, cc = idx & 3;    // 128 rows x 4 chunks of 16B
            uint32_t da = Ab + (uint32_t)(row * (S1 * 2) + cc * 16);
            const __half* pa = A + (long long)(row0 + row) * lda + k0 + cc * 8;
            asm volatile("cp.async.cg.shared.global [%0], [%1], 16;" :: "r"(da), "l"(pa));
            uint32_t db = Bb + (uint32_t)(row * (S1 * 2) + cc * 16);
            const __half* pb = B + (long long)(col0 + row) * ldb + k0 + cc * 8;
            asm volatile("cp.async.cg.shared.global [%0], [%1], 16;" :: "r"(db), "l"(pb));
        }
    };

    #pragma unroll
    for (int s = 0; s < STAGES; s++) {
        issue(s, s);
        asm volatile("cp.async.commit_group;");
    }

    for (int i = 0; i < nk; i++) {
        const int s = i % STAGES;
        asm volatile("cp.async.wait_group %0;" :: "n"(STAGES - 1));
        __syncthreads();
        const __half* As = smh + s * (STAGE1 / 2);
        const __half* Bs = As + ST1F;

        #pragma unroll
        for (int kk = 0; kk < 32; kk += 16) {
            uint32_t af[4][4], bf[4][2];
            #pragma unroll
            for (int mt = 0; mt < 4; mt++) {
                int rm = wm * 64 + mt * 16 + (lane >> 2);
                const __half* p0 = As + rm * S1 + kk + (lane & 3) * 2;
                af[mt][0] = *(const uint32_t*)(p0);
                af[mt][1] = *(const uint32_t*)(p0 + 8 * S1);
                af[mt][2] = *(const uint32_t*)(p0 + 8);
                af[mt][3] = *(const uint32_t*)(p0 + 8 * S1 + 8);
            }
            #pragma unroll
            for (int nt = 0; nt < 4; nt++) {
                int cn = wn * 32 + nt * 8 + (lane >> 2);
                const __half* p0 = Bs + cn * S1 + kk + (lane & 3) * 2;
                bf[nt][0] = *(const uint32_t*)(p0);
                bf[nt][1] = *(const uint32_t*)(p0 + 8);
            }
            #pragma unroll
            for (int mt = 0; mt < 4; mt++)
                #pragma unroll
                for (int nt = 0; nt < 4; nt++)
                    MMA_F16(acc[mt][nt], af[mt], bf[nt]);
        }
        __syncthreads();
        if (i + STAGES < nk) issue(i + STAGES, s);
        asm volatile("cp.async.commit_group;");
    }

    // epilogue: c0:(r,c) c1:(r,c+1) c2:(r+8,c) c3:(r+8,c+1)
    #pragma unroll
    for (int mt = 0; mt < 4; mt++) {
        #pragma unroll
        for (int nt = 0; nt < 4; nt++) {
            int r_ = row0 + wm * 64 + mt * 16 + (lane >> 2);
            int c_ = col0 + wn * 32 + nt * 8 + (lane & 3) * 2;
            #pragma unroll
            for (int half = 0; half < 2; half++) {
                int r = r_ + half * 8;
                float v0 = acc[mt][nt][half * 2 + 0] + (bias ? bias[c_] : 0.0f);
                float v1 = acc[mt][nt][half * 2 + 1] + (bias ? bias[c_ + 1] : 0.0f);
                if (CMODE == 1) {
                    int b_ = r >> 11, s_ = r & 2047;
                    int h0 = c_ / headW, d0 = c_ % headW;   // pairs never straddle heads
                    st_pair(&C[(((long long)(b_ * NH + h0)) * SEQ + s_) * DH + destOff + d0],
                            v0, v1);
                } else if (CMODE == 2) {
                    int b_ = r >> 11, s_ = r & 2047;
                    int h0 = c_ / DH, d0 = c_ % DH;
                    st_one(&C[(((long long)(b_ * NH + h0)) * DH + d0) * SEQ + s_], v0);
                    int h1 = (c_ + 1) / DH, d1 = (c_ + 1) % DH;
                    st_one(&C[(((long long)(b_ * NH + h1)) * DH + d1) * SEQ + s_], v1);
                } else {
                    st_pair(&C[(long long)r * ldc + c_], v0, v1);
                }
            }
        }
    }
}

// ---------------- 256x128 fp16 GEMM (batched over z), plain C ---------------
template<typename OUTT>
__global__ void __launch_bounds__(256, 1)
gemm256h(const __half* __restrict__ A, const __half* __restrict__ B,
         const float* __restrict__ bias, OUTT* __restrict__ C,
         int K, int lda, int ldb, int ldc,
         long long sA, long long sB, long long sC1, long long sC2, int zdiv)
{
    extern __shared__ __half smh[];
    const uint32_t sb = smem_u32(smh);
    const int tid = threadIdx.x, lane = tid & 31, wid = tid >> 5;
    const int wm = wid >> 1, wn = wid & 1;       // 4 (m) x 2 (n), warp 64x64
    const int z = blockIdx.z;
    A += (long long)z * sA;
    B += (long long)z * sB;
    const long long cbase = (long long)(z / zdiv) * sC1 + (long long)(z % zdiv) * sC2;
    const int row0 = blockIdx.y * 256, col0 = blockIdx.x * 128;

    float acc[4][8][4];
    #pragma unroll
    for (int a = 0; a < 4; a++)
        #pragma unroll
        for (int b = 0; b < 8; b++)
            #pragma unroll
            for (int c = 0; c < 4; c++) acc[a][b][c] = 0.0f;

    const int nk = K >> 6;   // KC = 64 halves

    auto issue = [&](int ch, int s) {
        const int k0 = ch << 6;
        const uint32_t Ab = sb + s * STAGE2;
        const uint32_t Bb = Ab + 256 * S2 * 2;
        #pragma unroll
        for (int t = 0; t < 8; t++) {            // A: 256 rows x 8 chunks
            int idx = tid + t * 256;
            int row = idx >> 3, cc = idx & 7;
            uint32_t da = Ab + (uint32_t)(row * (S2 * 2) + cc * 16);
            const __half* pa = A + (long long)(row0 + row) * lda + k0 + cc * 8;
            asm volatile("cp.async.cg.shared.global [%0], [%1], 16;" :: "r"(da), "l"(pa));
        }
        #pragma unroll
        for (int t = 0; t < 4; t++) {            // B: 128 rows x 8 chunks
            int idx = tid + t * 256;
            int row = idx >> 3, cc = idx & 7;
            uint32_t db = Bb + (uint32_t)(row * (S2 * 2) + cc * 16);
            const __half* pb = B + (long long)(col0 + row) * ldb + k0 + cc * 8;
            asm volatile("cp.async.cg.shared.global [%0], [%1], 16;" :: "r"(db), "l"(pb));
        }
    };

    #pragma unroll
    for (int s = 0; s < STAGES; s++) {
        issue(s, s);
        asm volatile("cp.async.commit_group;");
    }

    for (int i = 0; i < nk; i++) {
        const int s = i % STAGES;
        asm volatile("cp.async.wait_group %0;" :: "n"(STAGES - 1));
        __syncthreads();
        const __half* As = smh + s * (STAGE2 / 2);
        const __half* Bs = As + 256 * S2;

        #pragma unroll
        for (int kk = 0; kk < 64; kk += 16) {
            uint32_t af[4][4], bf[8][2];
            #pragma unroll
            for (int mt = 0; mt < 4; mt++) {
                int rm = wm * 64 + mt * 16 + (lane >> 2);
                const __half* p0 = As + rm * S2 + kk + (lane & 3) * 2;
                af[mt][0] = *(const uint32_t*)(p0);
                af[mt][1] = *(const uint32_t*)(p0 + 8 * S2);
                af[mt][2] = *(const uint32_t*)(p0 + 8);
                af[mt][3] = *(const uint32_t*)(p0 + 8 * S2 + 8);
            }
            #pragma unroll
            for (int nt = 0; nt < 8; nt++) {
                int cn = wn * 64 + nt * 8 + (lane >> 2);
                const __half* p0 = Bs + cn * S2 + kk + (lane & 3) * 2;
                bf[nt][0] = *(const uint32_t*)(p0);
                bf[nt][1] = *(const uint32_t*)(p0 + 8);
            }
            #pragma unroll
            for (int mt = 0; mt < 4; mt++)
                #pragma unroll
                for (int nt = 0; nt < 8; nt++)
                    MMA_F16(acc[mt][nt], af[mt], bf[nt]);
        }
        __syncthreads();
        if (i + STAGES < nk) issue(i + STAGES, s);
        asm volatile("cp.async.commit_group;");
    }

    #pragma unroll
    for (int mt = 0; mt < 4; mt++) {
        #pragma unroll
        for (int nt = 0; nt < 8; nt++) {
            int r_ = row0 + wm * 64 + mt * 16 + (lane >> 2);
            int c_ = col0 + wn * 64 + nt * 8 + (lane & 3) * 2;
            #pragma unroll
            for (int half = 0; half < 2; half++) {
                int r = r_ + half * 8;
                float v0 = acc[mt][nt][half * 2 + 0] + (bias ? bias[c_] : 0.0f);
                float v1 = acc[mt][nt][half * 2 + 1] + (bias ? bias[c_ + 1] : 0.0f);
                st_pair(&C[cbase + (long long)r * ldc + c_], v0, v1);
            }
        }
    }
}

// ---------------- transpose to half: dst[N][K] = half(src[K][N]) ------------
__global__ void __launch_bounds__(256)
transpose_h(const float* __restrict__ src, __half* __restrict__ dst, int K, int N)
{
    __shared__ float t[32][33];
    const int bn = blockIdx.x * 32, bk = blockIdx.y * 32;
    const int tx = threadIdx.x & 31, ty = threadIdx.x >> 5;
    #pragma unroll
    for (int j = 0; j < 4; j++)
        t[ty + 8 * j][tx] = src[(long long)(bk + ty + 8 * j) * N + bn + tx];
    __syncthreads();
    #pragma unroll
    for (int j = 0; j < 4; j++)
        dst[(long long)(bn + ty + 8 * j) * K + bk + tx] = __float2half_rn(t[tx][ty + 8 * j]);
}

// ---------------- fp32 -> fp16 pass (float4 granularity) --------------------
__global__ void to_half4(const float* __restrict__ src, __half* __restrict__ dst,
                         long long n4)
{
    long long i = (long long)blockIdx.x * blockDim.x + threadIdx.x;
    if (i >= n4) return;
    float4 v = ((const float4*)src)[i];
    ((__half2*)dst)[i * 2]     = __floats2half2_rn(v.x, v.y);
    ((__half2*)dst)[i * 2 + 1] = __floats2half2_rn(v.z, v.w);
}

// ---------------- bias gather for fused down-proj ---------------------------
__global__ void gather_bias(const float* b0, const float* b1, const float* b2,
                            float* dst)
{
    int i = threadIdx.x + blockIdx.x * blockDim.x;
    if (i >= 384) return;
    dst[i] = (i < 128) ? b0[i] : (i < 256) ? b1[i - 128] : b2[i - 256];
}

// ---------------- RoPE: rotate first 8 of 16, scatter to dst[...,624:640] ---
__global__ void rope_h(const __half* __restrict__ src, int sstride,
                       __half* __restrict__ dst)
{
    int t = blockIdx.x * blockDim.x + threadIdx.x;
    if (t >= ROWS * NH) return;
    int r = t / NH, h = t % NH;
    int b_ = r / SEQ, s = r % SEQ;
    const __half* x = src + (long long)r * sstride + h * 16;
    __half* o = dst + (((long long)(b_ * NH + h)) * SEQ + s) * DH + SPLITD;

    float tpos = (float)s / 40.0f;
    #pragma unroll
    for (int j = 0; j < 4; j++) {
        float invf = powf(10000.0f, -0.25f * (float)j);
        float f = tpos * invf;
        float cs = cosf(f), sn = sinf(f);
        float x1 = __half2float(x[j]), x2 = __half2float(x[j + 4]);
        o[j]     = __float2half_rn(x1 * cs - x2 * sn);
        o[j + 4] = __float2half_rn(x2 * cs + x1 * sn);
    }
    #pragma unroll
    for (int j = 8; j < 16; j++) o[j] = x[j];
}

// ---------------- row softmax fp32 -> half (with 1/sqrt(640) scale) ---------
__global__ void __launch_bounds__(256)
softmax_h(const float* __restrict__ sc, __half* __restrict__ at)
{
    long long row = blockIdx.x;
    const float* p = sc + row * SEQ;
    __half* pa = at + row * SEQ;
    const float scale = rsqrtf(640.0f);
    int tid = threadIdx.x;
    __shared__ float red[256];

    float vals[8];
    float mx = -1e30f;
    #pragma unroll
    for (int i = 0; i < 8; i++) {
        vals[i] = p[tid + i * 256] * scale;
        mx = fmaxf(mx, vals[i]);
    }
    red[tid] = mx; __syncthreads();
    for (int s = 128; s > 0; s >>= 1) {
        if (tid < s) red[tid] = fmaxf(red[tid], red[tid + s]);
        __syncthreads();
    }
    mx = red[0]; __syncthreads();

    float sum = 0.0f;
    #pragma unroll
    for (int i = 0; i < 8; i++) { vals[i] = __expf(vals[i] - mx); sum += vals[i]; }
    red[tid] = sum; __syncthreads();
    for (int s = 128; s > 0; s >>= 1) {
        if (tid < s) red[tid] += red[tid + s];
        __syncthreads();
    }
    float inv = 1.0f / red[0];
    #pragma unroll
    for (int i = 0; i < 8; i++) pa[tid + i * 256] = __float2half_rn(vals[i] * inv);
}

// ---------------- launch ----------------------------------------------------
extern "C" void kernel_launch(void* const* d_in, const int* in_sizes, int n_in,
                              void* d_out, int out_size)
{
    const float* h     = (const float*)d_in[0];
    const float* W_dkv = (const float*)d_in[1];
    const float* b_dkv = (const float*)d_in[2];
    const float* W_dq  = (const float*)d_in[3];
    const float* b_dq  = (const float*)d_in[4];
    const float* W_uk  = (const float*)d_in[5];
    const float* b_uk  = (const float*)d_in[6];
    const float* W_uv  = (const float*)d_in[7];
    const float* b_uv  = (const float*)d_in[8];
    const float* W_uq  = (const float*)d_in[9];
    const float* b_uq  = (const float*)d_in[10];
    const float* W_qr  = (const float*)d_in[11];
    const float* b_qr  = (const float*)d_in[12];
    const float* W_kr  = (const float*)d_in[13];
    const float* b_kr  = (const float*)d_in[14];
    const float* W_o   = (const float*)d_in[15];
    const float* b_o   = (const float*)d_in[16];
    float* out = (float*)d_out;

    __half *hh, *cdown, *qr, *q, *k, *vT, *at, *ao;
    __half *WdownT, *WukT, *WuvT, *WuqT, *WqrT, *WoT;
    float *bdown, *sc;
    cudaGetSymbolAddress((void**)&hh,    g_hh);
    cudaGetSymbolAddress((void**)&cdown, g_cdown);
    cudaGetSymbolAddress((void**)&bdown, g_bdown);
    cudaGetSymbolAddress((void**)&qr,    g_qr);
    cudaGetSymbolAddress((void**)&q,     g_q);
    cudaGetSymbolAddress((void**)&k,     g_k);
    cudaGetSymbolAddress((void**)&vT,    g_vT);
    cudaGetSymbolAddress((void**)&sc,    g_sc);
    cudaGetSymbolAddress((void**)&at,    g_at);
    cudaGetSymbolAddress((void**)&ao,    g_ao);
    cudaGetSymbolAddress((void**)&WdownT, g_WdownT);
    cudaGetSymbolAddress((void**)&WukT,  g_WukT);
    cudaGetSymbolAddress((void**)&WuvT,  g_WuvT);
    cudaGetSymbolAddress((void**)&WuqT,  g_WuqT);
    cudaGetSymbolAddress((void**)&WqrT,  g_WqrT);
    cudaGetSymbolAddress((void**)&WoT,   g_WoT);

    cudaFuncSetAttribute(gemm128h<0, __half>, cudaFuncAttributeMaxDynamicSharedMemorySize, SMEM1);
    cudaFuncSetAttribute(gemm128h<1, __half>, cudaFuncAttributeMaxDynamicSharedMemorySize, SMEM1);
    cudaFuncSetAttribute(gemm128h<2, __half>, cudaFuncAttributeMaxDynamicSharedMemorySize, SMEM1);
    cudaFuncSetAttribute(gemm256h<float>,  cudaFuncAttributeMaxDynamicSharedMemorySize, SMEM2);
    cudaFuncSetAttribute(gemm256h<__half>, cudaFuncAttributeMaxDynamicSharedMemorySize, SMEM2);

    // 0) h -> half
    {
        long long n4 = (long long)ROWS * DM / 4;
        to_half4<<<(unsigned)((n4 + 255) / 256), 256>>>(h, hh, n4);
    }

    // weight transposes (fp32 -> half): dst[N][K] = src[K][N]
    transpose_h<<<dim3(DKV/32, DM/32), 256>>>(W_dkv, WdownT,          DM, DKV);
    transpose_h<<<dim3(DKV/32, DM/32), 256>>>(W_dq,  WdownT + 128*DM, DM, DKV);
    transpose_h<<<dim3(128/32, DM/32), 256>>>(W_kr,  WdownT + 256*DM, DM, 128);
    transpose_h<<<dim3((NH*SPLITD)/32, DKV/32), 256>>>(W_uk, WukT, DKV, NH*SPLITD);
    transpose_h<<<dim3((NH*DH)/32,     DKV/32), 256>>>(W_uv, WuvT, DKV, NH*DH);
    transpose_h<<<dim3((NH*SPLITD)/32, DKV/32), 256>>>(W_uq, WuqT, DKV, NH*SPLITD);
    transpose_h<<<dim3(128/32,         DKV/32), 256>>>(W_qr, WqrT, DKV, 128);
    transpose_h<<<dim3(DM/32, DM/32),  256>>>(W_o, WoT, DM, DM);
    gather_bias<<<2, 192>>>(b_dkv, b_dq, b_kr, bdown);

    // 1) fused down-projections: [4096,5120] x [5120,384] -> cdown (half)
    gemm128h<0, __half><<<dim3(3,32),256,SMEM1>>>(hh, WdownT, bdown, cdown,
        DM, DM, DM, 384, 0,0);

    // 2) up-projections
    gemm128h<1, __half><<<dim3(39,32),256,SMEM1>>>(cdown, WukT, b_uk, k,
        DKV, 384, DKV, 0, SPLITD,0);
    gemm128h<2, __half><<<dim3(40,32),256,SMEM1>>>(cdown, WuvT, b_uv, vT,
        DKV, 384, DKV, 0, DH,0);
    gemm128h<1, __half><<<dim3(39,32),256,SMEM1>>>(cdown + 128, WuqT, b_uq, q,
        DKV, 384, DKV, 0, SPLITD,0);
    gemm128h<0, __half><<<dim3(1,32),256,SMEM1>>>(cdown + 128, WqrT, b_qr, qr,
        DKV, 384, DKV, 128, 0,0);

    // 3) RoPE scatter into q/k [...,624:640]
    rope_h<<<(ROWS*NH + 255)/256, 256>>>(qr, 128, q);
    rope_h<<<(ROWS*NH + 255)/256, 256>>>(cdown + 256, 384, k);

    // 4) scores = q @ k^T per head (z = bh) -> fp32; softmax applies scale
    gemm256h<float><<<dim3(16,8,16),256,SMEM2>>>(q, k, nullptr, sc,
        DH, DH, DH, SEQ,
        (long long)SEQ*DH, (long long)SEQ*DH, 0LL, (long long)SEQ*SEQ, 16);

    // 5) softmax fp32 -> half attn
    softmax_h<<<NB*NH*SEQ, 256>>>(sc, at);

    // 6) attn @ v (B = vT, K-major [640][2048]) -> ao half [b][s][h*640]
    gemm256h<__half><<<dim3(5,8,16),256,SMEM2>>>(at, vT, nullptr, ao,
        SEQ, SEQ, SEQ, DM,
        (long long)SEQ*SEQ, (long long)DH*SEQ,
        (long long)SEQ*DM, (long long)DH, NH);

    // 7) final: [4096,5120] x [5120,5120] + b_o -> fp32 out
    gemm256h<float><<<dim3(40,16,1),256,SMEM2>>>(ao, WoT, b_o, out,
        DM, DM, DM, DM, 0LL,0LL,0LL,0LL,1);
}

// round 10
// speedup vs baseline: 14.6169x; 1.7689x over previous
#include <cuda_runtime.h>
#include <cuda_fp16.h>
#include <cstdint>

#define SEQ   2048
#define NH    8
#define DH    640
#define DKV   128
#define NB    2
#define ROWS  (NB*SEQ)     // 4096
#define DM    5120
#define SPLITD 624
#define STAGES 3
// 128x128 fp16 kernel: KC=32 halves, stride 40 halves
#define S1    40
#define ST1F  (128*S1)
#define STAGE1 (2*ST1F*2)            // 20480 B
#define SMEM1 (STAGES*STAGE1)        // 61440
// 256x128 fp16 kernel: KC=64 halves, stride 72 halves
#define S2    72
#define STAGE2 ((256+128)*S2*2)      // 55296
#define SMEM2 (STAGES*STAGE2)        // 165888
#define KX    160                    // padded score K: 128 latent + 16 rope + 16 zero

// ---------------- scratch (device globals; allocation-free) ----------------
__device__ __half g_hh   [(size_t)ROWS*DM];
__device__ __half g_cdown[ROWS*384];                 // [ckv | cq | kr]
__device__ float  g_bdown[384];
__device__ __half g_qr  [ROWS*DKV];
__device__ __half g_qx  [(size_t)NB*NH*SEQ*KX];      // [bh][s][160]
__device__ __half g_kx  [(size_t)NB*NH*SEQ*KX];
__device__ __half g_Mt  [NH*DKV*DKV];                // [h][128][128]
__device__ float  g_wvec[NH*DKV];
__device__ __half g_ckvT[(size_t)NB*DKV*SEQ];        // [b][d][s]
__device__ float  g_sc  [(size_t)NB*NH*SEQ*SEQ];
__device__ __half g_at  [(size_t)NB*NH*SEQ*SEQ];
__device__ __half g_T   [(size_t)ROWS*NH*DKV];       // [b*s][h*128]
__device__ __half g_UT  [(size_t)DM*NH*DKV];         // [n][h*128+m]
__device__ float  g_bvec[DM];
// weights
__device__ __half g_WdownT[384*DM];                  // [W_dkv^T|W_dq^T|W_kr^T] K-major
__device__ __half g_WqrT [DKV*DKV];
__device__ __half g_WoT  [(size_t)DM*DM];            // W_o^T [n][m]
__device__ __half g_Wukp [DKV*NH*DH];                // per-head padded 624->640
__device__ __half g_Wuqp [DKV*NH*DH];
__device__ __half g_Wuvh [DKV*NH*DH];                // plain half copy

// ---------------- helpers ---------------------------------------------------
__device__ __forceinline__ uint32_t smem_u32(const void* p) {
    uint32_t a;
    asm("{ .reg .u64 t; cvta.to.shared.u64 t, %1; cvt.u32.u64 %0, t; }"
        : "=r"(a) : "l"(p));
    return a;
}

#define MMA_F16(acc, af, bf) \
    asm volatile( \
        "mma.sync.aligned.m16n8k16.row.col.f32.f16.f16.f32 " \
        "{%0,%1,%2,%3}, {%4,%5,%6,%7}, {%8,%9}, {%0,%1,%2,%3};" \
        : "+f"((acc)[0]), "+f"((acc)[1]), "+f"((acc)[2]), "+f"((acc)[3]) \
        : "r"((af)[0]), "r"((af)[1]), "r"((af)[2]), "r"((af)[3]), \
          "r"((bf)[0]), "r"((bf)[1]))

__device__ __forceinline__ void st_pair(float* p, float a, float b) {
    *(float2*)p = make_float2(a, b);
}
__device__ __forceinline__ void st_pair(__half* p, float a, float b) {
    *(__half2*)p = __floats2half2_rn(a, b);
}
__device__ __forceinline__ void st_one(float* p, float a) { *p = a; }
__device__ __forceinline__ void st_one(__half* p, float a) { *p = __float2half_rn(a); }

// ---------------- 128x128 fp16 GEMM, z-batched: C = A[M,K] @ B[N,K]^T -------
// offsets per z: off = (z/zdiv)*s1 + (z%zdiv)*s2 (elements) for A, B, C.
// CMODE 0: C[cbase + r*ldc + c];  CMODE 2 (transposed): C[cbase + c*ldc + r]
template<int CMODE, typename OUTT>
__global__ void __launch_bounds__(256, 1)
gemm128z(const __half* __restrict__ A, const __half* __restrict__ B,
         const float* __restrict__ bias, int biasStride, OUTT* __restrict__ C,
         int K, int lda, int ldb, int ldc,
         long long sA1, long long sA2, long long sB1, long long sB2,
         long long sC1, long long sC2, int zdiv)
{
    extern __shared__ __half smh[];
    const uint32_t sb = smem_u32(smh);
    const int tid = threadIdx.x, lane = tid & 31, wid = tid >> 5;
    const int wm = wid >> 2, wn = wid & 3;       // 2 (m) x 4 (n), warp 64x32
    const int z = blockIdx.z;
    A += (long long)(z / zdiv) * sA1 + (long long)(z % zdiv) * sA2;
    B += (long long)(z / zdiv) * sB1 + (long long)(z % zdiv) * sB2;
    if (bias) bias += (z % zdiv) * biasStride;
    const long long cbase = (long long)(z / zdiv) * sC1 + (long long)(z % zdiv) * sC2;
    const int row0 = blockIdx.y * 128, col0 = blockIdx.x * 128;

    float acc[4][4][4];
    #pragma unroll
    for (int a = 0; a < 4; a++)
        #pragma unroll
        for (int b = 0; b < 4; b++)
            #pragma unroll
            for (int c = 0; c < 4; c++) acc[a][b][c] = 0.0f;

    const int nk = K >> 5;   // KC = 32 halves

    auto issue = [&](int ch, int s) {
        const int k0 = ch << 5;
        const uint32_t Ab = sb + s * STAGE1;
        const uint32_t Bb = Ab + ST1F * 2;
        #pragma unroll
        for (int t = 0; t < 2; t++) {
            int idx = tid + t * 256;
            int row = idx >> 2, cc = idx & 3;
            uint32_t da = Ab + (uint32_t)(row * (S1 * 2) + cc * 16);
            const __half* pa = A + (long long)(row0 + row) * lda + k0 + cc * 8;
            asm volatile("cp.async.cg.shared.global [%0], [%1], 16;" :: "r"(da), "l"(pa));
            uint32_t db = Bb + (uint32_t)(row * (S1 * 2) + cc * 16);
            const __half* pb = B + (long long)(col0 + row) * ldb + k0 + cc * 8;
            asm volatile("cp.async.cg.shared.global [%0], [%1], 16;" :: "r"(db), "l"(pb));
        }
    };

    #pragma unroll
    for (int s = 0; s < STAGES; s++) {
        issue(s, s);
        asm volatile("cp.async.commit_group;");
    }

    for (int i = 0; i < nk; i++) {
        const int s = i % STAGES;
        asm volatile("cp.async.wait_group %0;" :: "n"(STAGES - 1));
        __syncthreads();
        const __half* As = smh + s * (STAGE1 / 2);
        const __half* Bs = As + ST1F;

        #pragma unroll
        for (int kk = 0; kk < 32; kk += 16) {
            uint32_t af[4][4], bf[4][2];
            #pragma unroll
            for (int mt = 0; mt < 4; mt++) {
                int rm = wm * 64 + mt * 16 + (lane >> 2);
                const __half* p0 = As + rm * S1 + kk + (lane & 3) * 2;
                af[mt][0] = *(const uint32_t*)(p0);
                af[mt][1] = *(const uint32_t*)(p0 + 8 * S1);
                af[mt][2] = *(const uint32_t*)(p0 + 8);
                af[mt][3] = *(const uint32_t*)(p0 + 8 * S1 + 8);
            }
            #pragma unroll
            for (int nt = 0; nt < 4; nt++) {
                int cn = wn * 32 + nt * 8 + (lane >> 2);
                const __half* p0 = Bs + cn * S1 + kk + (lane & 3) * 2;
                bf[nt][0] = *(const uint32_t*)(p0);
                bf[nt][1] = *(const uint32_t*)(p0 + 8);
            }
            #pragma unroll
            for (int mt = 0; mt < 4; mt++)
                #pragma unroll
                for (int nt = 0; nt < 4; nt++)
                    MMA_F16(acc[mt][nt], af[mt], bf[nt]);
        }
        __syncthreads();
        if (i + STAGES < nk) issue(i + STAGES, s);
        asm volatile("cp.async.commit_group;");
    }

    #pragma unroll
    for (int mt = 0; mt < 4; mt++) {
        #pragma unroll
        for (int nt = 0; nt < 4; nt++) {
            int r_ = row0 + wm * 64 + mt * 16 + (lane >> 2);
            int c_ = col0 + wn * 32 + nt * 8 + (lane & 3) * 2;
            #pragma unroll
            for (int half = 0; half < 2; half++) {
                int r = r_ + half * 8;
                float v0 = acc[mt][nt][half * 2 + 0] + (bias ? bias[c_] : 0.0f);
                float v1 = acc[mt][nt][half * 2 + 1] + (bias ? bias[c_ + 1] : 0.0f);
                if (CMODE == 2) {
                    st_one(&C[cbase + (long long)c_ * ldc + r], v0);
                    st_one(&C[cbase + (long long)(c_ + 1) * ldc + r], v1);
                } else {
                    st_pair(&C[cbase + (long long)r * ldc + c_], v0, v1);
                }
            }
        }
    }
}

// ---------------- 256x128 fp16 GEMM (final output GEMM) ---------------------
template<typename OUTT>
__global__ void __launch_bounds__(256, 1)
gemm256h(const __half* __restrict__ A, const __half* __restrict__ B,
         const float* __restrict__ bias, OUTT* __restrict__ C,
         int K, int lda, int ldb, int ldc)
{
    extern __shared__ __half smh[];
    const uint32_t sb = smem_u32(smh);
    const int tid = threadIdx.x, lane = tid & 31, wid = tid >> 5;
    const int wm = wid >> 1, wn = wid & 1;       // 4 (m) x 2 (n), warp 64x64
    const int row0 = blockIdx.y * 256, col0 = blockIdx.x * 128;

    float acc[4][8][4];
    #pragma unroll
    for (int a = 0; a < 4; a++)
        #pragma unroll
        for (int b = 0; b < 8; b++)
            #pragma unroll
            for (int c = 0; c < 4; c++) acc[a][b][c] = 0.0f;

    const int nk = K >> 6;   // KC = 64 halves

    auto issue = [&](int ch, int s) {
        const int k0 = ch << 6;
        const uint32_t Ab = sb + s * STAGE2;
        const uint32_t Bb = Ab + 256 * S2 * 2;
        #pragma unroll
        for (int t = 0; t < 8; t++) {
            int idx = tid + t * 256;
            int row = idx >> 3, cc = idx & 7;
            uint32_t da = Ab + (uint32_t)(row * (S2 * 2) + cc * 16);
            const __half* pa = A + (long long)(row0 + row) * lda + k0 + cc * 8;
            asm volatile("cp.async.cg.shared.global [%0], [%1], 16;" :: "r"(da), "l"(pa));
        }
        #pragma unroll
        for (int t = 0; t < 4; t++) {
            int idx = tid + t * 256;
            int row = idx >> 3, cc = idx & 7;
            uint32_t db = Bb + (uint32_t)(row * (S2 * 2) + cc * 16);
            const __half* pb = B + (long long)(col0 + row) * ldb + k0 + cc * 8;
            asm volatile("cp.async.cg.shared.global [%0], [%1], 16;" :: "r"(db), "l"(pb));
        }
    };

    #pragma unroll
    for (int s = 0; s < STAGES; s++) {
        issue(s, s);
        asm volatile("cp.async.commit_group;");
    }

    for (int i = 0; i < nk; i++) {
        const int s = i % STAGES;
        asm volatile("cp.async.wait_group %0;" :: "n"(STAGES - 1));
        __syncthreads();
        const __half* As = smh + s * (STAGE2 / 2);
        const __half* Bs = As + 256 * S2;

        #pragma unroll
        for (int kk = 0; kk < 64; kk += 16) {
            uint32_t af[4][4], bf[8][2];
            #pragma unroll
            for (int mt = 0; mt < 4; mt++) {
                int rm = wm * 64 + mt * 16 + (lane >> 2);
                const __half* p0 = As + rm * S2 + kk + (lane & 3) * 2;
                af[mt][0] = *(const uint32_t*)(p0);
                af[mt][1] = *(const uint32_t*)(p0 + 8 * S2);
                af[mt][2] = *(const uint32_t*)(p0 + 8);
                af[mt][3] = *(const uint32_t*)(p0 + 8 * S2 + 8);
            }
            #pragma unroll
            for (int nt = 0; nt < 8; nt++) {
                int cn = wn * 64 + nt * 8 + (lane >> 2);
                const __half* p0 = Bs + cn * S2 + kk + (lane & 3) * 2;
                bf[nt][0] = *(const uint32_t*)(p0);
                bf[nt][1] = *(const uint32_t*)(p0 + 8);
            }
            #pragma unroll
            for (int mt = 0; mt < 4; mt++)
                #pragma unroll
                for (int nt = 0; nt < 8; nt++)
                    MMA_F16(acc[mt][nt], af[mt], bf[nt]);
        }
        __syncthreads();
        if (i + STAGES < nk) issue(i + STAGES, s);
        asm volatile("cp.async.commit_group;");
    }

    #pragma unroll
    for (int mt = 0; mt < 4; mt++) {
        #pragma unroll
        for (int nt = 0; nt < 8; nt++) {
            int r_ = row0 + wm * 64 + mt * 16 + (lane >> 2);
            int c_ = col0 + wn * 64 + nt * 8 + (lane & 3) * 2;
            #pragma unroll
            for (int half = 0; half < 2; half++) {
                int r = r_ + half * 8;
                float v0 = acc[mt][nt][half * 2 + 0] + (bias ? bias[c_] : 0.0f);
                float v1 = acc[mt][nt][half * 2 + 1] + (bias ? bias[c_ + 1] : 0.0f);
                st_pair(&C[(long long)r * ldc + c_], v0, v1);
            }
        }
    }
}

// ---------------- transpose to half: dst[N][K] = half(src[K][N]) ------------
__global__ void __launch_bounds__(256)
transpose_h(const float* __restrict__ src, __half* __restrict__ dst, int K, int N)
{
    __shared__ float t[32][33];
    const int bn = blockIdx.x * 32, bk = blockIdx.y * 32;
    const int tx = threadIdx.x & 31, ty = threadIdx.x >> 5;
    #pragma unroll
    for (int j = 0; j < 4; j++)
        t[ty + 8 * j][tx] = src[(long long)(bk + ty + 8 * j) * N + bn + tx];
    __syncthreads();
    #pragma unroll
    for (int j = 0; j < 4; j++)
        dst[(long long)(bn + ty + 8 * j) * K + bk + tx] = __float2half_rn(t[tx][ty + 8 * j]);
}

// ---------------- fp32 -> fp16 pass -----------------------------------------
__global__ void to_half4(const float* __restrict__ src, __half* __restrict__ dst,
                         long long n4)
{
    long long i = (long long)blockIdx.x * blockDim.x + threadIdx.x;
    if (i >= n4) return;
    float4 v = ((const float4*)src)[i];
    ((__half2*)dst)[i * 2]     = __floats2half2_rn(v.x, v.y);
    ((__half2*)dst)[i * 2 + 1] = __floats2half2_rn(v.z, v.w);
}

// ---------------- per-head pad repack: [128,4992] -> [128, 8*640] half ------
__global__ void repack_pad(const float* __restrict__ src, __half* __restrict__ dst)
{
    int i = blockIdx.x * blockDim.x + threadIdx.x;
    if (i >= DKV * NH * DH) return;
    int r = i / (NH * DH), c = i % (NH * DH);
    int h = c / DH, d = c % DH;
    float v = (d < SPLITD) ? src[(long long)r * (NH * SPLITD) + h * SPLITD + d] : 0.0f;
    dst[i] = __float2half_rn(v);
}

// ---------------- bias gather for fused down-proj ---------------------------
__global__ void gather_bias(const float* b0, const float* b1, const float* b2,
                            float* dst)
{
    int i = threadIdx.x + blockIdx.x * blockDim.x;
    if (i >= 384) return;
    dst[i] = (i < 128) ? b0[i] : (i < 256) ? b1[i - 128] : b2[i - 256];
}

// ---------------- wvec[h][d] = sum_t W_uk[d, h*624+t] * b_uq[h*624+t] -------
__global__ void calc_wvec(const float* __restrict__ Wuk,
                          const float* __restrict__ b_uq, float* __restrict__ w)
{
    int hh = blockIdx.x, d = threadIdx.x;   // 8 x 128
    float acc = 0.0f;
    for (int t = 0; t < SPLITD; t++)
        acc += Wuk[(long long)d * (NH * SPLITD) + hh * SPLITD + t] * b_uq[hh * SPLITD + t];
    w[hh * DKV + d] = acc;
}

// ---------------- bvec[n] = b_uv @ W_o[:,n] + b_o[n] ------------------------
__global__ void __launch_bounds__(256)
calc_bvec(const float* __restrict__ b_uv, const float* __restrict__ Wo,
          const float* __restrict__ b_o, float* __restrict__ bvec)
{
    int c = blockIdx.x * 128 + (threadIdx.x & 127);
    int part = threadIdx.x >> 7;
    float acc = 0.0f;
    for (int m = part * 2560; m < part * 2560 + 2560; m++)
        acc += b_uv[m] * Wo[(long long)m * DM + c];
    __shared__ float red[256];
    red[threadIdx.x] = acc; __syncthreads();
    if (part == 0) bvec[c] = red[threadIdx.x] + red[threadIdx.x + 128] + b_o[c];
}

// ---------------- build kx cols 0..127 (copy ckv per head) ------------------
__global__ void build_kx(const __half* __restrict__ cdown, __half* __restrict__ kx)
{
    long long i = (long long)blockIdx.x * blockDim.x + threadIdx.x;
    if (i >= (long long)NB * NH * SEQ * 16) return;
    long long zs = i >> 4; int chunk = (int)(i & 15);
    long long z = zs >> 11, s = zs & 2047;
    long long b = z >> 3;
    const uint4* srcp = (const uint4*)(cdown + ((b << 11) + s) * 384) + chunk;
    ((uint4*)(kx + zs * KX))[chunk] = *srcp;
}

// ---------------- rope into qx/kx cols 128..143 + zero 144..159 -------------
template<int ISQ>
__global__ void rope_fill(const __half* __restrict__ src, __half* __restrict__ dst)
{
    int t = blockIdx.x * blockDim.x + threadIdx.x;
    if (t >= NB * NH * SEQ) return;
    int z = t >> 11, s = t & 2047;
    int b_ = z >> 3, hh = z & 7;
    const __half* x = ISQ ? src + ((long long)((b_ << 11) + s)) * 128 + hh * 16
                          : src + ((long long)((b_ << 11) + s)) * 384 + 256 + hh * 16;
    __half* o = dst + (long long)t * KX + 128;

    float tpos = (float)s / 40.0f;
    #pragma unroll
    for (int j = 0; j < 4; j++) {
        float invf = powf(10000.0f, -0.25f * (float)j);
        float f = tpos * invf;
        float cs = cosf(f), sn = sinf(f);
        float x1 = __half2float(x[j]), x2 = __half2float(x[j + 4]);
        o[j]     = __float2half_rn(x1 * cs - x2 * sn);
        o[j + 4] = __float2half_rn(x2 * cs + x1 * sn);
    }
    #pragma unroll
    for (int j = 8; j < 16; j++) o[j] = x[j];
    *(uint4*)(o + 16) = make_uint4(0, 0, 0, 0);
    *(uint4*)(o + 24) = make_uint4(0, 0, 0, 0);
}

// ---------------- ckvT[b][d][s] = cdown[b*2048+s][d] ------------------------
__global__ void __launch_bounds__(256)
transpose_ckv(const __half* __restrict__ cdown, __half* __restrict__ ckvT)
{
    __shared__ __half t[32][34];
    const int b = blockIdx.z;
    const int d0 = blockIdx.x * 32, s0 = blockIdx.y * 32;
    const int tx = threadIdx.x & 31, ty = threadIdx.x >> 5;
    #pragma unroll
    for (int j = 0; j < 4; j++)
        t[ty + 8 * j][tx] = cdown[((long long)b * SEQ + s0 + ty + 8 * j) * 384 + d0 + tx];
    __syncthreads();
    #pragma unroll
    for (int j = 0; j < 4; j++)
        ckvT[((long long)b * DKV + d0 + ty + 8 * j) * SEQ + s0 + tx] = t[tx][ty + 8 * j];
}

// ---------------- row softmax fp32 -> half ----------------------------------
__global__ void __launch_bounds__(256)
softmax_h(const float* __restrict__ sc, __half* __restrict__ at)
{
    long long row = blockIdx.x;
    const float* p = sc + row * SEQ;
    __half* pa = at + row * SEQ;
    const float scale = rsqrtf(640.0f);
    int tid = threadIdx.x;
    __shared__ float red[256];

    float vals[8];
    float mx = -1e30f;
    #pragma unroll
    for (int i = 0; i < 8; i++) {
        vals[i] = p[tid + i * 256] * scale;
        mx = fmaxf(mx, vals[i]);
    }
    red[tid] = mx; __syncthreads();
    for (int s = 128; s > 0; s >>= 1) {
        if (tid < s) red[tid] = fmaxf(red[tid], red[tid + s]);
        __syncthreads();
    }
    mx = red[0]; __syncthreads();

    float sum = 0.0f;
    #pragma unroll
    for (int i = 0; i < 8; i++) { vals[i] = __expf(vals[i] - mx); sum += vals[i]; }
    red[tid] = sum; __syncthreads();
    for (int s = 128; s > 0; s >>= 1) {
        if (tid < s) red[tid] += red[tid + s];
        __syncthreads();
    }
    float inv = 1.0f / red[0];
    #pragma unroll
    for (int i = 0; i < 8; i++) pa[tid + i * 256] = __float2half_rn(vals[i] * inv);
}

// ---------------- launch ----------------------------------------------------
extern "C" void kernel_launch(void* const* d_in, const int* in_sizes, int n_in,
                              void* d_out, int out_size)
{
    const float* h     = (const float*)d_in[0];
    const float* W_dkv = (const float*)d_in[1];
    const float* b_dkv = (const float*)d_in[2];
    const float* W_dq  = (const float*)d_in[3];
    const float* b_dq  = (const float*)d_in[4];
    const float* W_uk  = (const float*)d_in[5];
    const float* b_uk  = (const float*)d_in[6];   // softmax-invariant; dropped
    const float* W_uv  = (const float*)d_in[7];
    const float* b_uv  = (const float*)d_in[8];
    const float* W_uq  = (const float*)d_in[9];
    const float* b_uq  = (const float*)d_in[10];
    const float* W_qr  = (const float*)d_in[11];
    const float* b_qr  = (const float*)d_in[12];
    const float* W_kr  = (const float*)d_in[13];
    const float* b_kr  = (const float*)d_in[14];
    const float* W_o   = (const float*)d_in[15];
    const float* b_o   = (const float*)d_in[16];
    float* out = (float*)d_out;
    (void)b_uk;

    __half *hh, *cdown, *qr, *qx, *kx, *Mt, *ckvT, *at, *T, *UT;
    __half *WdownT, *WqrT, *WoT, *Wukp, *Wuqp, *Wuvh;
    float *bdown, *wvec, *sc, *bvec;
    cudaGetSymbolAddress((void**)&hh,    g_hh);
    cudaGetSymbolAddress((void**)&cdown, g_cdown);
    cudaGetSymbolAddress((void**)&bdown, g_bdown);
    cudaGetSymbolAddress((void**)&qr,    g_qr);
    cudaGetSymbolAddress((void**)&qx,    g_qx);
    cudaGetSymbolAddress((void**)&kx,    g_kx);
    cudaGetSymbolAddress((void**)&Mt,    g_Mt);
    cudaGetSymbolAddress((void**)&wvec,  g_wvec);
    cudaGetSymbolAddress((void**)&ckvT,  g_ckvT);
    cudaGetSymbolAddress((void**)&sc,    g_sc);
    cudaGetSymbolAddress((void**)&at,    g_at);
    cudaGetSymbolAddress((void**)&T,     g_T);
    cudaGetSymbolAddress((void**)&UT,    g_UT);
    cudaGetSymbolAddress((void**)&bvec,  g_bvec);
    cudaGetSymbolAddress((void**)&WdownT, g_WdownT);
    cudaGetSymbolAddress((void**)&WqrT,  g_WqrT);
    cudaGetSymbolAddress((void**)&WoT,   g_WoT);
    cudaGetSymbolAddress((void**)&Wukp,  g_Wukp);
    cudaGetSymbolAddress((void**)&Wuqp,  g_Wuqp);
    cudaGetSymbolAddress((void**)&Wuvh,  g_Wuvh);

    cudaFuncSetAttribute(gemm128z<0, __half>, cudaFuncAttributeMaxDynamicSharedMemorySize, SMEM1);
    cudaFuncSetAttribute(gemm128z<0, float>,  cudaFuncAttributeMaxDynamicSharedMemorySize, SMEM1);
    cudaFuncSetAttribute(gemm128z<2, __half>, cudaFuncAttributeMaxDynamicSharedMemorySize, SMEM1);
    cudaFuncSetAttribute(gemm256h<float>, cudaFuncAttributeMaxDynamicSharedMemorySize, SMEM2);

    const long long ZSEQKX = (long long)SEQ * KX;      // qx/kx per-z stride
    const long long ZSS    = (long long)SEQ * SEQ;

    // ---- weight prep ----
    {
        long long n4 = (long long)ROWS * DM / 4;
        to_half4<<<(unsigned)((n4 + 255) / 256), 256>>>(h, hh, n4);
    }
    transpose_h<<<dim3(DKV/32, DM/32), 256>>>(W_dkv, WdownT,          DM, DKV);
    transpose_h<<<dim3(DKV/32, DM/32), 256>>>(W_dq,  WdownT + 128*DM, DM, DKV);
    transpose_h<<<dim3(128/32, DM/32), 256>>>(W_kr,  WdownT + 256*DM, DM, 128);
    transpose_h<<<dim3(DKV/32, DKV/32), 256>>>(W_qr, WqrT, DKV, DKV);
    transpose_h<<<dim3(DM/32, DM/32),  256>>>(W_o, WoT, DM, DM);
    repack_pad<<<(DKV*NH*DH + 255)/256, 256>>>(W_uk, Wukp);
    repack_pad<<<(DKV*NH*DH + 255)/256, 256>>>(W_uq, Wuqp);
    {
        long long n4 = (long long)DKV * NH * DH / 4;
        to_half4<<<(unsigned)((n4 + 255) / 256), 256>>>(W_uv, Wuvh, n4);
    }
    gather_bias<<<2, 192>>>(b_dkv, b_dq, b_kr, bdown);
    calc_wvec<<<NH, DKV>>>(W_uk, b_uq, wvec);
    calc_bvec<<<DM/128, 256>>>(b_uv, W_o, b_o, bvec);

    // ---- Mt[h] = W_uk^h @ W_uq^h^T  [128,128], K=640 (padded per head) ----
    gemm128z<0, __half><<<dim3(1,1,NH),256,SMEM1>>>(Wukp, Wuqp, nullptr, 0, Mt,
        DH, NH*DH, NH*DH, DKV,
        0, DH, 0, DH, 0, (long long)DKV*DKV, NH);

    // ---- U^h = W_uv^h @ W_o^h -> UT[n][h*128+m], K=640 ----
    gemm128z<2, __half><<<dim3(DM/128,1,NH),256,SMEM1>>>(Wuvh, WoT, nullptr, 0, UT,
        DH, NH*DH, DM, NH*DKV,
        0, DH, 0, DH, 0, DKV, NH);

    // ---- down: cdown = hh @ WdownT^T + bdown  [4096,384], K=5120 ----
    gemm128z<0, __half><<<dim3(3,32,1),256,SMEM1>>>(hh, WdownT, bdown, 0, cdown,
        DM, DM, DM, 384, 0,0, 0,0, 0,0, 1);

    // ---- qr = c_q @ WqrT^T + b_qr  [4096,128], K=128 ----
    gemm128z<0, __half><<<dim3(1,32,1),256,SMEM1>>>(cdown + 128, WqrT, b_qr, 0, qr,
        DKV, 384, DKV, DKV, 0,0, 0,0, 0,0, 1);

    // ---- qeff: qx[z][s][0..127] = c_q[b] @ Mt[h]^T + wvec[h], K=128 ----
    gemm128z<0, __half><<<dim3(1,16,NB*NH),256,SMEM1>>>(cdown + 128, Mt, wvec, DKV, qx,
        DKV, 384, DKV, KX,
        (long long)SEQ*384, 0, 0, (long long)DKV*DKV,
        8*ZSEQKX, ZSEQKX, NH);

    // ---- kx latent copy + rope fills + ckvT ----
    build_kx<<<(unsigned)(((long long)NB*NH*SEQ*16 + 255)/256), 256>>>(cdown, kx);
    rope_fill<1><<<(NB*NH*SEQ + 255)/256, 256>>>(qr, qx);
    rope_fill<0><<<(NB*NH*SEQ + 255)/256, 256>>>(cdown, kx);
    transpose_ckv<<<dim3(DKV/32, SEQ/32, NB), 256>>>(cdown, ckvT);

    // ---- scores = qx @ kx^T  fp32, K=160 ----
    gemm128z<0, float><<<dim3(16,16,NB*NH),256,SMEM1>>>(qx, kx, nullptr, 0, sc,
        KX, KX, KX, SEQ,
        8*ZSEQKX, ZSEQKX, 8*ZSEQKX, ZSEQKX,
        8*ZSS, ZSS, NH);

    // ---- softmax ----
    softmax_h<<<NB*NH*SEQ, 256>>>(sc, at);

    // ---- t = at @ ckvT^T -> T[b*s][h*128+d], K=2048 ----
    gemm128z<0, __half><<<dim3(1,16,NB*NH),256,SMEM1>>>(at, ckvT, nullptr, 0, T,
        SEQ, SEQ, SEQ, NH*DKV,
        8*ZSS, ZSS, (long long)DKV*SEQ, 0,
        (long long)SEQ*NH*DKV, DKV, NH);

    // ---- out = T @ UT^T + bvec  [4096,5120], K=1024 ----
    gemm256h<float><<<dim3(DM/128, ROWS/256, 1),256,SMEM2>>>(T, UT, bvec, out,
        NH*DKV, NH*DKV, NH*DKV, DM);
}

// round 12
// speedup vs baseline: 19.5588x; 1.3381x over previous
#include <cuda_runtime.h>
#include <cuda_fp16.h>
#include <cstdint>

#define SEQ   2048
#define NH    8
#define DH    640
#define DKV   128
#define NB    2
#define ROWS  (NB*SEQ)     // 4096
#define DM    5120
#define SPLITD 624
#define STAGES 3
// 128x128 fp16 kernel: KC=32 halves, stride 40 halves
#define S1    40
#define ST1F  (128*S1)
#define STAGE1 (2*ST1F*2)            // 20480 B
#define SMEM1 (STAGES*STAGE1)        // 61440
// 256x128 fp16 kernel, KC=64: stride 72 halves
#define S2    72
#define STAGE2 ((256+128)*S2*2)      // 55296
#define SMEM2 (STAGES*STAGE2)        // 165888
// 256x128 fp16 kernel, KC=32: stride 40 halves (z-batched)
#define STAGE3 ((256+128)*S1*2)      // 30720 B
#define SMEM3 (STAGES*STAGE3)        // 92160
#define KX    160                    // padded score K: 128 latent + 16 rope + 16 zero

// ---------------- scratch (device globals; allocation-free) ----------------
__device__ __half g_hh   [(size_t)ROWS*DM];
__device__ __half g_cdown[ROWS*384];                 // [ckv | cq | kr]
__device__ float  g_bdown[384];
__device__ __half g_qr  [ROWS*DKV];
__device__ __half g_qx  [(size_t)NB*NH*SEQ*KX];      // [bh][s][160]
__device__ __half g_kx  [(size_t)NB*NH*SEQ*KX];
__device__ __half g_Mt  [NH*DKV*DKV];                // [h][128][128]
__device__ float  g_wvec[NH*DKV];
__device__ __half g_ckvT[(size_t)NB*DKV*SEQ];        // [b][d][s]
__device__ __half g_sc  [(size_t)NB*NH*SEQ*SEQ];     // half scores (pre-scale)
__device__ __half g_at  [(size_t)NB*NH*SEQ*SEQ];
__device__ __half g_T   [(size_t)ROWS*NH*DKV];       // [b*s][h*128]
__device__ __half g_UT  [(size_t)DM*NH*DKV];         // [n][h*128+m]
__device__ float  g_bvec[DM];
// weights
__device__ __half g_WdownT[384*DM];                  // [W_dkv^T|W_dq^T|W_kr^T] K-major
__device__ __half g_WqrT [DKV*DKV];
__device__ __half g_WoT  [(size_t)DM*DM];            // W_o^T [n][m]
__device__ __half g_Wukp [DKV*NH*DH];                // per-head padded 624->640
__device__ __half g_Wuqp [DKV*NH*DH];
__device__ __half g_Wuvh [DKV*NH*DH];                // plain half copy

// ---------------- helpers ---------------------------------------------------
__device__ __forceinline__ uint32_t smem_u32(const void* p) {
    uint32_t a;
    asm("{ .reg .u64 t; cvta.to.shared.u64 t, %1; cvt.u32.u64 %0, t; }"
        : "=r"(a) : "l"(p));
    return a;
}

#define MMA_F16(acc, af, bf) \
    asm volatile( \
        "mma.sync.aligned.m16n8k16.row.col.f32.f16.f16.f32 " \
        "{%0,%1,%2,%3}, {%4,%5,%6,%7}, {%8,%9}, {%0,%1,%2,%3};" \
        : "+f"((acc)[0]), "+f"((acc)[1]), "+f"((acc)[2]), "+f"((acc)[3]) \
        : "r"((af)[0]), "r"((af)[1]), "r"((af)[2]), "r"((af)[3]), \
          "r"((bf)[0]), "r"((bf)[1]))

__device__ __forceinline__ void st_pair(float* p, float a, float b) {
    *(float2*)p = make_float2(a, b);
}
__device__ __forceinline__ void st_pair(__half* p, float a, float b) {
    *(__half2*)p = __floats2half2_rn(a, b);
}
__device__ __forceinline__ void st_one(float* p, float a) { *p = a; }
__device__ __forceinline__ void st_one(__half* p, float a) { *p = __float2half_rn(a); }

// ---------------- 128x128 fp16 GEMM, z-batched: C = A[M,K] @ B[N,K]^T -------
// offsets per z: off = (z/zdiv)*s1 + (z%zdiv)*s2 (elements) for A, B, C.
// CMODE 0: C[cbase + r*ldc + c];  CMODE 2 (transposed): C[cbase + c*ldc + r]
template<int CMODE, typename OUTT>
__global__ void __launch_bounds__(256, 1)
gemm128z(const __half* __restrict__ A, const __half* __restrict__ B,
         const float* __restrict__ bias, int biasStride, OUTT* __restrict__ C,
         int K, int lda, int ldb, int ldc,
         long long sA1, long long sA2, long long sB1, long long sB2,
         long long sC1, long long sC2, int zdiv)
{
    extern __shared__ __half smh[];
    const uint32_t sb = smem_u32(smh);
    const int tid = threadIdx.x, lane = tid & 31, wid = tid >> 5;
    const int wm = wid >> 2, wn = wid & 3;       // 2 (m) x 4 (n), warp 64x32
    const int z = blockIdx.z;
    A += (long long)(z / zdiv) * sA1 + (long long)(z % zdiv) * sA2;
    B += (long long)(z / zdiv) * sB1 + (long long)(z % zdiv) * sB2;
    if (bias) bias += (z % zdiv) * biasStride;
    const long long cbase = (long long)(z / zdiv) * sC1 + (long long)(z % zdiv) * sC2;
    const int row0 = blockIdx.y * 128, col0 = blockIdx.x * 128;

    float acc[4][4][4];
    #pragma unroll
    for (int a = 0; a < 4; a++)
        #pragma unroll
        for (int b = 0; b < 4; b++)
            #pragma unroll
            for (int c = 0; c < 4; c++) acc[a][b][c] = 0.0f;

    const int nk = K >> 5;   // KC = 32 halves

    auto issue = [&](int ch, int s) {
        const int k0 = ch << 5;
        const uint32_t Ab = sb + s * STAGE1;
        const uint32_t Bb = Ab + ST1F * 2;
        #pragma unroll
        for (int t = 0; t < 2; t++) {
            int idx = tid + t * 256;
            int row = idx >> 2, cc = idx & 3;
            uint32_t da = Ab + (uint32_t)(row * (S1 * 2) + cc * 16);
            const __half* pa = A + (long long)(row0 + row) * lda + k0 + cc * 8;
            asm volatile("cp.async.cg.shared.global [%0], [%1], 16;" :: "r"(da), "l"(pa));
            uint32_t db = Bb + (uint32_t)(row * (S1 * 2) + cc * 16);
            const __half* pb = B + (long long)(col0 + row) * ldb + k0 + cc * 8;
            asm volatile("cp.async.cg.shared.global [%0], [%1], 16;" :: "r"(db), "l"(pb));
        }
    };

    #pragma unroll
    for (int s = 0; s < STAGES; s++) {
        issue(s, s);
        asm volatile("cp.async.commit_group;");
    }

    for (int i = 0; i < nk; i++) {
        const int s = i % STAGES;
        asm volatile("cp.async.wait_group %0;" :: "n"(STAGES - 1));
        __syncthreads();
        const __half* As = smh + s * (STAGE1 / 2);
        const __half* Bs = As + ST1F;

        #pragma unroll
        for (int kk = 0; kk < 32; kk += 16) {
            uint32_t af[4][4], bf[4][2];
            #pragma unroll
            for (int mt = 0; mt < 4; mt++) {
                int rm = wm * 64 + mt * 16 + (lane >> 2);
                const __half* p0 = As + rm * S1 + kk + (lane & 3) * 2;
                af[mt][0] = *(const uint32_t*)(p0);
                af[mt][1] = *(const uint32_t*)(p0 + 8 * S1);
                af[mt][2] = *(const uint32_t*)(p0 + 8);
                af[mt][3] = *(const uint32_t*)(p0 + 8 * S1 + 8);
            }
            #pragma unroll
            for (int nt = 0; nt < 4; nt++) {
                int cn = wn * 32 + nt * 8 + (lane >> 2);
                const __half* p0 = Bs + cn * S1 + kk + (lane & 3) * 2;
                bf[nt][0] = *(const uint32_t*)(p0);
                bf[nt][1] = *(const uint32_t*)(p0 + 8);
            }
            #pragma unroll
            for (int mt = 0; mt < 4; mt++)
                #pragma unroll
                for (int nt = 0; nt < 4; nt++)
                    MMA_F16(acc[mt][nt], af[mt], bf[nt]);
        }
        __syncthreads();
        if (i + STAGES < nk) issue(i + STAGES, s);
        asm volatile("cp.async.commit_group;");
    }

    #pragma unroll
    for (int mt = 0; mt < 4; mt++) {
        #pragma unroll
        for (int nt = 0; nt < 4; nt++) {
            int r_ = row0 + wm * 64 + mt * 16 + (lane >> 2);
            int c_ = col0 + wn * 32 + nt * 8 + (lane & 3) * 2;
            #pragma unroll
            for (int half = 0; half < 2; half++) {
                int r = r_ + half * 8;
                float v0 = acc[mt][nt][half * 2 + 0] + (bias ? bias[c_] : 0.0f);
                float v1 = acc[mt][nt][half * 2 + 1] + (bias ? bias[c_ + 1] : 0.0f);
                if (CMODE == 2) {
                    st_one(&C[cbase + (long long)c_ * ldc + r], v0);
                    st_one(&C[cbase + (long long)(c_ + 1) * ldc + r], v1);
                } else {
                    st_pair(&C[cbase + (long long)r * ldc + c_], v0, v1);
                }
            }
        }
    }
}

// ---------------- 256x128 fp16 GEMM, KC=64 (final output GEMM) --------------
template<typename OUTT>
__global__ void __launch_bounds__(256, 1)
gemm256h(const __half* __restrict__ A, const __half* __restrict__ B,
         const float* __restrict__ bias, OUTT* __restrict__ C,
         int K, int lda, int ldb, int ldc)
{
    extern __shared__ __half smh[];
    const uint32_t sb = smem_u32(smh);
    const int tid = threadIdx.x, lane = tid & 31, wid = tid >> 5;
    const int wm = wid >> 1, wn = wid & 1;       // 4 (m) x 2 (n), warp 64x64
    const int row0 = blockIdx.y * 256, col0 = blockIdx.x * 128;

    float acc[4][8][4];
    #pragma unroll
    for (int a = 0; a < 4; a++)
        #pragma unroll
        for (int b = 0; b < 8; b++)
            #pragma unroll
            for (int c = 0; c < 4; c++) acc[a][b][c] = 0.0f;

    const int nk = K >> 6;   // KC = 64 halves

    auto issue = [&](int ch, int s) {
        const int k0 = ch << 6;
        const uint32_t Ab = sb + s * STAGE2;
        const uint32_t Bb = Ab + 256 * S2 * 2;
        #pragma unroll
        for (int t = 0; t < 8; t++) {
            int idx = tid + t * 256;
            int row = idx >> 3, cc = idx & 7;
            uint32_t da = Ab + (uint32_t)(row * (S2 * 2) + cc * 16);
            const __half* pa = A + (long long)(row0 + row) * lda + k0 + cc * 8;
            asm volatile("cp.async.cg.shared.global [%0], [%1], 16;" :: "r"(da), "l"(pa));
        }
        #pragma unroll
        for (int t = 0; t < 4; t++) {
            int idx = tid + t * 256;
            int row = idx >> 3, cc = idx & 7;
            uint32_t db = Bb + (uint32_t)(row * (S2 * 2) + cc * 16);
            const __half* pb = B + (long long)(col0 + row) * ldb + k0 + cc * 8;
            asm volatile("cp.async.cg.shared.global [%0], [%1], 16;" :: "r"(db), "l"(pb));
        }
    };

    #pragma unroll
    for (int s = 0; s < STAGES; s++) {
        issue(s, s);
        asm volatile("cp.async.commit_group;");
    }

    for (int i = 0; i < nk; i++) {
        const int s = i % STAGES;
        asm volatile("cp.async.wait_group %0;" :: "n"(STAGES - 1));
        __syncthreads();
        const __half* As = smh + s * (STAGE2 / 2);
        const __half* Bs = As + 256 * S2;

        #pragma unroll
        for (int kk = 0; kk < 64; kk += 16) {
            uint32_t af[4][4], bf[8][2];
            #pragma unroll
            for (int mt = 0; mt < 4; mt++) {
                int rm = wm * 64 + mt * 16 + (lane >> 2);
                const __half* p0 = As + rm * S2 + kk + (lane & 3) * 2;
                af[mt][0] = *(const uint32_t*)(p0);
                af[mt][1] = *(const uint32_t*)(p0 + 8 * S2);
                af[mt][2] = *(const uint32_t*)(p0 + 8);
                af[mt][3] = *(const uint32_t*)(p0 + 8 * S2 + 8);
            }
            #pragma unroll
            for (int nt = 0; nt < 8; nt++) {
                int cn = wn * 64 + nt * 8 + (lane >> 2);
                const __half* p0 = Bs + cn * S2 + kk + (lane & 3) * 2;
                bf[nt][0] = *(const uint32_t*)(p0);
                bf[nt][1] = *(const uint32_t*)(p0 + 8);
            }
            #pragma unroll
            for (int mt = 0; mt < 4; mt++)
                #pragma unroll
                for (int nt = 0; nt < 8; nt++)
                    MMA_F16(acc[mt][nt], af[mt], bf[nt]);
        }
        __syncthreads();
        if (i + STAGES < nk) issue(i + STAGES, s);
        asm volatile("cp.async.commit_group;");
    }

    #pragma unroll
    for (int mt = 0; mt < 4; mt++) {
        #pragma unroll
        for (int nt = 0; nt < 8; nt++) {
            int r_ = row0 + wm * 64 + mt * 16 + (lane >> 2);
            int c_ = col0 + wn * 64 + nt * 8 + (lane & 3) * 2;
            #pragma unroll
            for (int half = 0; half < 2; half++) {
                int r = r_ + half * 8;
                float v0 = acc[mt][nt][half * 2 + 0] + (bias ? bias[c_] : 0.0f);
                float v1 = acc[mt][nt][half * 2 + 1] + (bias ? bias[c_ + 1] : 0.0f);
                st_pair(&C[(long long)r * ldc + c_], v0, v1);
            }
        }
    }
}

// ---------------- 256x128 fp16 GEMM, KC=32, z-batched, no bias --------------
// C[cbase + r*ldc + c]; per-z offsets like gemm128z.
template<typename OUTT>
__global__ void __launch_bounds__(256, 1)
gemm256z(const __half* __restrict__ A, const __half* __restrict__ B,
         OUTT* __restrict__ C,
         int K, int lda, int ldb, int ldc,
         long long sA1, long long sA2, long long sB1, long long sB2,
         long long sC1, long long sC2, int zdiv)
{
    extern __shared__ __half smh[];
    const uint32_t sb = smem_u32(smh);
    const int tid = threadIdx.x, lane = tid & 31, wid = tid >> 5;
    const int wm = wid >> 1, wn = wid & 1;       // 4 (m) x 2 (n), warp 64x64
    const int z = blockIdx.z;
    A += (long long)(z / zdiv) * sA1 + (long long)(z % zdiv) * sA2;
    B += (long long)(z / zdiv) * sB1 + (long long)(z % zdiv) * sB2;
    const long long cbase = (long long)(z / zdiv) * sC1 + (long long)(z % zdiv) * sC2;
    const int row0 = blockIdx.y * 256, col0 = blockIdx.x * 128;

    float acc[4][8][4];
    #pragma unroll
    for (int a = 0; a < 4; a++)
        #pragma unroll
        for (int b = 0; b < 8; b++)
            #pragma unroll
            for (int c = 0; c < 4; c++) acc[a][b][c] = 0.0f;

    const int nk = K >> 5;   // KC = 32 halves (nk >= 3 required; K >= 96)

    auto issue = [&](int ch, int s) {
        const int k0 = ch << 5;
        const uint32_t Ab = sb + s * STAGE3;
        const uint32_t Bb = Ab + 256 * S1 * 2;
        #pragma unroll
        for (int t = 0; t < 4; t++) {            // A: 256 rows x 4 chunks
            int idx = tid + t * 256;
            int row = idx >> 2, cc = idx & 3;
            uint32_t da = Ab + (uint32_t)(row * (S1 * 2) + cc * 16);
            const __half* pa = A + (long long)(row0 + row) * lda + k0 + cc * 8;
            asm volatile("cp.async.cg.shared.global [%0], [%1], 16;" :: "r"(da), "l"(pa));
        }
        #pragma unroll
        for (int t = 0; t < 2; t++) {            // B: 128 rows x 4 chunks
            int idx = tid + t * 256;
            int row = idx >> 2, cc = idx & 3;
            uint32_t db = Bb + (uint32_t)(row * (S1 * 2) + cc * 16);
            const __half* pb = B + (long long)(col0 + row) * ldb + k0 + cc * 8;
            asm volatile("cp.async.cg.shared.global [%0], [%1], 16;" :: "r"(db), "l"(pb));
        }
    };

    #pragma unroll
    for (int s = 0; s < STAGES; s++) {
        issue(s, s);
        asm volatile("cp.async.commit_group;");
    }

    for (int i = 0; i < nk; i++) {
        const int s = i % STAGES;
        asm volatile("cp.async.wait_group %0;" :: "n"(STAGES - 1));
        __syncthreads();
        const __half* As = smh + s * (STAGE3 / 2);
        const __half* Bs = As + 256 * S1;

        #pragma unroll
        for (int kk = 0; kk < 32; kk += 16) {
            uint32_t af[4][4], bf[8][2];
            #pragma unroll
            for (int mt = 0; mt < 4; mt++) {
                int rm = wm * 64 + mt * 16 + (lane >> 2);
                const __half* p0 = As + rm * S1 + kk + (lane & 3) * 2;
                af[mt][0] = *(const uint32_t*)(p0);
                af[mt][1] = *(const uint32_t*)(p0 + 8 * S1);
                af[mt][2] = *(const uint32_t*)(p0 + 8);
                af[mt][3] = *(const uint32_t*)(p0 + 8 * S1 + 8);
            }
            #pragma unroll
            for (int nt = 0; nt < 8; nt++) {
                int cn = wn * 64 + nt * 8 + (lane >> 2);
                const __half* p0 = Bs + cn * S1 + kk + (lane & 3) * 2;
                bf[nt][0] = *(const uint32_t*)(p0);
                bf[nt][1] = *(const uint32_t*)(p0 + 8);
            }
            #pragma unroll
            for (int mt = 0; mt < 4; mt++)
                #pragma unroll
                for (int nt = 0; nt < 8; nt++)
                    MMA_F16(acc[mt][nt], af[mt], bf[nt]);
        }
        __syncthreads();
        if (i + STAGES < nk) issue(i + STAGES, s);
        asm volatile("cp.async.commit_group;");
    }

    #pragma unroll
    for (int mt = 0; mt < 4; mt++) {
        #pragma unroll
        for (int nt = 0; nt < 8; nt++) {
            int r_ = row0 + wm * 64 + mt * 16 + (lane >> 2);
            int c_ = col0 + wn * 64 + nt * 8 + (lane & 3) * 2;
            #pragma unroll
            for (int half = 0; half < 2; half++) {
                int r = r_ + half * 8;
                st_pair(&C[cbase + (long long)r * ldc + c_],
                        acc[mt][nt][half * 2 + 0], acc[mt][nt][half * 2 + 1]);
            }
        }
    }
}

// ---------------- transpose to half: dst[N][K] = half(src[K][N]) ------------
__global__ void __launch_bounds__(256)
transpose_h(const float* __restrict__ src, __half* __restrict__ dst, int K, int N)
{
    __shared__ float t[32][33];
    const int bn = blockIdx.x * 32, bk = blockIdx.y * 32;
    const int tx = threadIdx.x & 31, ty = threadIdx.x >> 5;
    #pragma unroll
    for (int j = 0; j < 4; j++)
        t[ty + 8 * j][tx] = src[(long long)(bk + ty + 8 * j) * N + bn + tx];
    __syncthreads();
    #pragma unroll
    for (int j = 0; j < 4; j++)
        dst[(long long)(bn + ty + 8 * j) * K + bk + tx] = __float2half_rn(t[tx][ty + 8 * j]);
}

// ---------------- fp32 -> fp16 pass -----------------------------------------
__global__ void to_half4(const float* __restrict__ src, __half* __restrict__ dst,
                         long long n4)
{
    long long i = (long long)blockIdx.x * blockDim.x + threadIdx.x;
    if (i >= n4) return;
    float4 v = ((const float4*)src)[i];
    ((__half2*)dst)[i * 2]     = __floats2half2_rn(v.x, v.y);
    ((__half2*)dst)[i * 2 + 1] = __floats2half2_rn(v.z, v.w);
}

// ---------------- per-head pad repack: [128,4992] -> [128, 8*640] half ------
__global__ void repack_pad(const float* __restrict__ src, __half* __restrict__ dst)
{
    int i = blockIdx.x * blockDim.x + threadIdx.x;
    if (i >= DKV * NH * DH) return;
    int r = i / (NH * DH), c = i % (NH * DH);
    int h = c / DH, d = c % DH;
    float v = (d < SPLITD) ? src[(long long)r * (NH * SPLITD) + h * SPLITD + d] : 0.0f;
    dst[i] = __float2half_rn(v);
}

// ---------------- bias gather for fused down-proj ---------------------------
__global__ void gather_bias(const float* b0, const float* b1, const float* b2,
                            float* dst)
{
    int i = threadIdx.x + blockIdx.x * blockDim.x;
    if (i >= 384) return;
    dst[i] = (i < 128) ? b0[i] : (i < 256) ? b1[i - 128] : b2[i - 256];
}

// ---------------- wvec[h][d] = sum_t W_uk[d, h*624+t] * b_uq[h*624+t] -------
__global__ void calc_wvec(const float* __restrict__ Wuk,
                          const float* __restrict__ b_uq, float* __restrict__ w)
{
    int hh = blockIdx.x, d = threadIdx.x;   // 8 x 128
    float acc = 0.0f;
    for (int t = 0; t < SPLITD; t++)
        acc += Wuk[(long long)d * (NH * SPLITD) + hh * SPLITD + t] * b_uq[hh * SPLITD + t];
    w[hh * DKV + d] = acc;
}

// ---------------- bvec[c] = b_uv @ W_o[:,c] + b_o[c], from WoT (half) -------
__global__ void __launch_bounds__(256)
calc_bvec2(const float* __restrict__ b_uv, const __half* __restrict__ WoT,
           const float* __restrict__ b_o, float* __restrict__ bvec)
{
    int wid = threadIdx.x >> 5, lane = threadIdx.x & 31;
    int c = blockIdx.x * 8 + wid;
    const __half2* row = (const __half2*)(WoT + (long long)c * DM);
    float acc = 0.0f;
    for (int m2 = lane; m2 < DM / 2; m2 += 32) {
        __half2 v = row[m2];
        acc += __half2float(v.x) * b_uv[m2 * 2] + __half2float(v.y) * b_uv[m2 * 2 + 1];
    }
    #pragma unroll
    for (int o = 16; o > 0; o >>= 1)
        acc += __shfl_xor_sync(0xFFFFFFFFu, acc, o);
    if (lane == 0) bvec[c] = acc + b_o[c];
}

// ---------------- build kx cols 0..127 (copy ckv per head) ------------------
__global__ void build_kx(const __half* __restrict__ cdown, __half* __restrict__ kx)
{
    long long i = (long long)blockIdx.x * blockDim.x + threadIdx.x;
    if (i >= (long long)NB * NH * SEQ * 16) return;
    long long zs = i >> 4; int chunk = (int)(i & 15);
    long long z = zs >> 11, s = zs & 2047;
    long long b = z >> 3;
    const uint4* srcp = (const uint4*)(cdown + ((b << 11) + s) * 384) + chunk;
    ((uint4*)(kx + zs * KX))[chunk] = *srcp;
}

// ---------------- rope into qx/kx cols 128..143 + zero 144..159 -------------
template<int ISQ>
__global__ void rope_fill(const __half* __restrict__ src, __half* __restrict__ dst)
{
    int t = blockIdx.x * blockDim.x + threadIdx.x;
    if (t >= NB * NH * SEQ) return;
    int z = t >> 11, s = t & 2047;
    int b_ = z >> 3, hh = z & 7;
    const __half* x = ISQ ? src + ((long long)((b_ << 11) + s)) * 128 + hh * 16
                          : src + ((long long)((b_ << 11) + s)) * 384 + 256 + hh * 16;
    __half* o = dst + (long long)t * KX + 128;

    float tpos = (float)s / 40.0f;
    #pragma unroll
    for (int j = 0; j < 4; j++) {
        float invf = powf(10000.0f, -0.25f * (float)j);
        float f = tpos * invf;
        float cs = cosf(f), sn = sinf(f);
        float x1 = __half2float(x[j]), x2 = __half2float(x[j + 4]);
        o[j]     = __float2half_rn(x1 * cs - x2 * sn);
        o[j + 4] = __float2half_rn(x2 * cs + x1 * sn);
    }
    #pragma unroll
    for (int j = 8; j < 16; j++) o[j] = x[j];
    *(uint4*)(o + 16) = make_uint4(0, 0, 0, 0);
    *(uint4*)(o + 24) = make_uint4(0, 0, 0, 0);
}

// ---------------- ckvT[b][d][s] = cdown[b*2048+s][d] ------------------------
__global__ void __launch_bounds__(256)
transpose_ckv(const __half* __restrict__ cdown, __half* __restrict__ ckvT)
{
    __shared__ __half t[32][34];
    const int b = blockIdx.z;
    const int d0 = blockIdx.x * 32, s0 = blockIdx.y * 32;
    const int tx = threadIdx.x & 31, ty = threadIdx.x >> 5;
    #pragma unroll
    for (int j = 0; j < 4; j++)
        t[ty + 8 * j][tx] = cdown[((long long)b * SEQ + s0 + ty + 8 * j) * 384 + d0 + tx];
    __syncthreads();
    #pragma unroll
    for (int j = 0; j < 4; j++)
        ckvT[((long long)b * DKV + d0 + ty + 8 * j) * SEQ + s0 + tx] = t[tx][ty + 8 * j];
}

// ---------------- row softmax: half in (pre-scale), half out ----------------
__global__ void __launch_bounds__(256)
softmax_h(const __half* __restrict__ sc, __half* __restrict__ at)
{
    long long row = blockIdx.x;
    const __half* p = sc + row * SEQ;
    __half* pa = at + row * SEQ;
    const float scale = rsqrtf(640.0f);
    int tid = threadIdx.x;
    __shared__ float red[256];

    uint4 raw = ((const uint4*)p)[tid];          // 8 halves, coalesced 16B
    __half2 h0 = *(__half2*)&raw.x, h1 = *(__half2*)&raw.y;
    __half2 h2 = *(__half2*)&raw.z, h3 = *(__half2*)&raw.w;
    float vals[8] = {
        __half2float(h0.x) * scale, __half2float(h0.y) * scale,
        __half2float(h1.x) * scale, __half2float(h1.y) * scale,
        __half2float(h2.x) * scale, __half2float(h2.y) * scale,
        __half2float(h3.x) * scale, __half2float(h3.y) * scale };

    float mx = vals[0];
    #pragma unroll
    for (int i = 1; i < 8; i++) mx = fmaxf(mx, vals[i]);
    red[tid] = mx; __syncthreads();
    for (int s = 128; s > 0; s >>= 1) {
        if (tid < s) red[tid] = fmaxf(red[tid], red[tid + s]);
        __syncthreads();
    }
    mx = red[0]; __syncthreads();

    float sum = 0.0f;
    #pragma unroll
    for (int i = 0; i < 8; i++) { vals[i] = __expf(vals[i] - mx); sum += vals[i]; }
    red[tid] = sum; __syncthreads();
    for (int s = 128; s > 0; s >>= 1) {
        if (tid < s) red[tid] += red[tid + s];
        __syncthreads();
    }
    float inv = 1.0f / red[0];

    uint4 outp;
    __half2 o0 = __floats2half2_rn(vals[0] * inv, vals[1] * inv);
    __half2 o1 = __floats2half2_rn(vals[2] * inv, vals[3] * inv);
    __half2 o2 = __floats2half2_rn(vals[4] * inv, vals[5] * inv);
    __half2 o3 = __floats2half2_rn(vals[6] * inv, vals[7] * inv);
    outp.x = *(uint32_t*)&o0; outp.y = *(uint32_t*)&o1;
    outp.z = *(uint32_t*)&o2; outp.w = *(uint32_t*)&o3;
    ((uint4*)pa)[tid] = outp;
}

// ---------------- launch ----------------------------------------------------
extern "C" void kernel_launch(void* const* d_in, const int* in_sizes, int n_in,
                              void* d_out, int out_size)
{
    const float* h     = (const float*)d_in[0];
    const float* W_dkv = (const float*)d_in[1];
    const float* b_dkv = (const float*)d_in[2];
    const float* W_dq  = (const float*)d_in[3];
    const float* b_dq  = (const float*)d_in[4];
    const float* W_uk  = (const float*)d_in[5];
    const float* b_uk  = (const float*)d_in[6];   // softmax-invariant; dropped
    const float* W_uv  = (const float*)d_in[7];
    const float* b_uv  = (const float*)d_in[8];
    const float* W_uq  = (const float*)d_in[9];
    const float* b_uq  = (const float*)d_in[10];
    const float* W_qr  = (const float*)d_in[11];
    const float* b_qr  = (const float*)d_in[12];
    const float* W_kr  = (const float*)d_in[13];
    const float* b_kr  = (const float*)d_in[14];
    const float* W_o   = (const float*)d_in[15];
    const float* b_o   = (const float*)d_in[16];
    float* out = (float*)d_out;
    (void)b_uk;

    __half *hh, *cdown, *qr, *qx, *kx, *Mt, *ckvT, *sc, *at, *T, *UT;
    __half *WdownT, *WqrT, *WoT, *Wukp, *Wuqp, *Wuvh;
    float *bdown, *wvec, *bvec;
    cudaGetSymbolAddress((void**)&hh,    g_hh);
    cudaGetSymbolAddress((void**)&cdown, g_cdown);
    cudaGetSymbolAddress((void**)&bdown, g_bdown);
    cudaGetSymbolAddress((void**)&qr,    g_qr);
    cudaGetSymbolAddress((void**)&qx,    g_qx);
    cudaGetSymbolAddress((void**)&kx,    g_kx);
    cudaGetSymbolAddress((void**)&Mt,    g_Mt);
    cudaGetSymbolAddress((void**)&wvec,  g_wvec);
    cudaGetSymbolAddress((void**)&ckvT,  g_ckvT);
    cudaGetSymbolAddress((void**)&sc,    g_sc);
    cudaGetSymbolAddress((void**)&at,    g_at);
    cudaGetSymbolAddress((void**)&T,     g_T);
    cudaGetSymbolAddress((void**)&UT,    g_UT);
    cudaGetSymbolAddress((void**)&bvec,  g_bvec);
    cudaGetSymbolAddress((void**)&WdownT, g_WdownT);
    cudaGetSymbolAddress((void**)&WqrT,  g_WqrT);
    cudaGetSymbolAddress((void**)&WoT,   g_WoT);
    cudaGetSymbolAddress((void**)&Wukp,  g_Wukp);
    cudaGetSymbolAddress((void**)&Wuqp,  g_Wuqp);
    cudaGetSymbolAddress((void**)&Wuvh,  g_Wuvh);

    cudaFuncSetAttribute(gemm128z<0, __half>, cudaFuncAttributeMaxDynamicSharedMemorySize, SMEM1);
    cudaFuncSetAttribute(gemm128z<2, __half>, cudaFuncAttributeMaxDynamicSharedMemorySize, SMEM1);
    cudaFuncSetAttribute(gemm256h<float>, cudaFuncAttributeMaxDynamicSharedMemorySize, SMEM2);
    cudaFuncSetAttribute(gemm256z<__half>, cudaFuncAttributeMaxDynamicSharedMemorySize, SMEM3);

    const long long ZSEQKX = (long long)SEQ * KX;      // qx/kx per-z stride
    const long long ZSS    = (long long)SEQ * SEQ;

    // ---- weight prep ----
    {
        long long n4 = (long long)ROWS * DM / 4;
        to_half4<<<(unsigned)((n4 + 255) / 256), 256>>>(h, hh, n4);
    }
    transpose_h<<<dim3(DKV/32, DM/32), 256>>>(W_dkv, WdownT,          DM, DKV);
    transpose_h<<<dim3(DKV/32, DM/32), 256>>>(W_dq,  WdownT + 128*DM, DM, DKV);
    transpose_h<<<dim3(128/32, DM/32), 256>>>(W_kr,  WdownT + 256*DM, DM, 128);
    transpose_h<<<dim3(DKV/32, DKV/32), 256>>>(W_qr, WqrT, DKV, DKV);
    transpose_h<<<dim3(DM/32, DM/32),  256>>>(W_o, WoT, DM, DM);
    repack_pad<<<(DKV*NH*DH + 255)/256, 256>>>(W_uk, Wukp);
    repack_pad<<<(DKV*NH*DH + 255)/256, 256>>>(W_uq, Wuqp);
    {
        long long n4 = (long long)DKV * NH * DH / 4;
        to_half4<<<(unsigned)((n4 + 255) / 256), 256>>>(W_uv, Wuvh, n4);
    }
    gather_bias<<<2, 192>>>(b_dkv, b_dq, b_kr, bdown);
    calc_wvec<<<NH, DKV>>>(W_uk, b_uq, wvec);
    calc_bvec2<<<DM/8, 256>>>(b_uv, WoT, b_o, bvec);   // after W_o transpose

    // ---- Mt[h] = W_uk^h @ W_uq^h^T  [128,128], K=640 (padded per head) ----
    gemm128z<0, __half><<<dim3(1,1,NH),256,SMEM1>>>(Wukp, Wuqp, nullptr, 0, Mt,
        DH, NH*DH, NH*DH, DKV,
        0, DH, 0, DH, 0, (long long)DKV*DKV, NH);

    // ---- U^h = W_uv^h @ W_o^h -> UT[n][h*128+m], K=640 ----
    gemm128z<2, __half><<<dim3(DM/128,1,NH),256,SMEM1>>>(Wuvh, WoT, nullptr, 0, UT,
        DH, NH*DH, DM, NH*DKV,
        0, DH, 0, DH, 0, DKV, NH);

    // ---- down: cdown = hh @ WdownT^T + bdown  [4096,384], K=5120 ----
    gemm128z<0, __half><<<dim3(3,32,1),256,SMEM1>>>(hh, WdownT, bdown, 0, cdown,
        DM, DM, DM, 384, 0,0, 0,0, 0,0, 1);

    // ---- qr = c_q @ WqrT^T + b_qr  [4096,128], K=128 ----
    gemm128z<0, __half><<<dim3(1,32,1),256,SMEM1>>>(cdown + 128, WqrT, b_qr, 0, qr,
        DKV, 384, DKV, DKV, 0,0, 0,0, 0,0, 1);

    // ---- qeff: qx[z][s][0..127] = c_q[b] @ Mt[h]^T + wvec[h], K=128 ----
    gemm128z<0, __half><<<dim3(1,16,NB*NH),256,SMEM1>>>(cdown + 128, Mt, wvec, DKV, qx,
        DKV, 384, DKV, KX,
        (long long)SEQ*384, 0, 0, (long long)DKV*DKV,
        8*ZSEQKX, ZSEQKX, NH);

    // ---- kx latent copy + rope fills + ckvT ----
    build_kx<<<(unsigned)(((long long)NB*NH*SEQ*16 + 255)/256), 256>>>(cdown, kx);
    rope_fill<1><<<(NB*NH*SEQ + 255)/256, 256>>>(qr, qx);
    rope_fill<0><<<(NB*NH*SEQ + 255)/256, 256>>>(cdown, kx);
    transpose_ckv<<<dim3(DKV/32, SEQ/32, NB), 256>>>(cdown, ckvT);

    // ---- scores = qx @ kx^T  (half out, pre-scale), K=160, 256x128 tiles ---
    gemm256z<__half><<<dim3(16,8,NB*NH),256,SMEM3>>>(qx, kx, sc,
        KX, KX, KX, SEQ,
        8*ZSEQKX, ZSEQKX, 8*ZSEQKX, ZSEQKX,
        8*ZSS, ZSS, NH);

    // ---- softmax (half in, scale applied, half out) ----
    softmax_h<<<NB*NH*SEQ, 256>>>(sc, at);

    // ---- t = at @ ckvT^T -> T[b*s][h*128+d], K=2048, 256x128 tiles ---------
    gemm256z<__half><<<dim3(1,8,NB*NH),256,SMEM3>>>(at, ckvT, T,
        SEQ, SEQ, SEQ, NH*DKV,
        8*ZSS, ZSS, (long long)DKV*SEQ, 0,
        (long long)SEQ*NH*DKV, DKV, NH);

    // ---- out = T @ UT^T + bvec  [4096,5120], K=1024 ----
    gemm256h<float><<<dim3(DM/128, ROWS/256, 1),256,SMEM2>>>(T, UT, bvec, out,
        NH*DKV, NH*DKV, NH*DKV, DM);
}